// round 10
// baseline (speedup 1.0000x reference)
#include <cuda_runtime.h>
#include <cuda_fp16.h>
#include <math.h>
#include <stdint.h>

#define LNUM 8
#define DMODEL 512
#define DINX 1024
#define DSX 16
#define SLEN 256
#define TTOT 512   // BATCH * SLEN tokens

// weight arena offsets (elements)
#define WTOT      26345472
#define OFF_PATCH 0
#define OFF_INPJ  393216
#define OFF_XPJ   8781824
#define OFF_DTW   9306112
#define OFF_OUTP  9568256
#define OFF_FC1   13762560
#define OFF_FC2   22151168

// ---------------- scratch (static device memory; no allocations) ----------------
__device__ float g_imgtok[128 * DMODEL];
__device__ float g_hidden[TTOT * DMODEL];
__device__ float g_resid[TTOT * DMODEL];
__device__ float g_xnorm[TTOT * DMODEL];
__device__ float g_xz[TTOT * 2 * DINX];
__device__ float g_xc[TTOT * DINX];
__device__ float g_proj[TTOT * 64];
__device__ float g_dt[TTOT * DINX];
__device__ float g_g[TTOT * 2 * DINX];
__device__ float g_Aneg[LNUM * DINX * DSX];
__device__ float g_part[4 * TTOT * DMODEL];
__device__ float g_la[128];

// fp16 hi/lo operand arenas
__device__ __half g_wh[WTOT], g_wl[WTOT];
__device__ __half g_mph[128 * 768], g_mpl[128 * 768];
__device__ __half g_xnh[TTOT * DMODEL], g_xnl[TTOT * DMODEL];
__device__ __half g_xch[TTOT * DINX], g_xcl[TTOT * DINX];
__device__ __half g_dtrh[TTOT * 32], g_dtrl[TTOT * 32];
__device__ __half g_ymh[TTOT * DINX], g_yml[TTOT * DINX];
__device__ __half g_uh[TTOT * DINX], g_ul[TTOT * DINX];

__device__ __forceinline__ float siluf(float x) { return x / (1.0f + __expf(-x)); }
__device__ __forceinline__ float softplusf(float x) {
    return fmaxf(x, 0.0f) + log1pf(__expf(-fabsf(x)));
}
__device__ __forceinline__ void hsplit(float v, __half* hp, __half* lp) {
    __half h = __float2half_rn(v);
    *hp = h;
    *lp = __float2half_rn(v - __half2float(h));
}

__device__ __forceinline__ uint32_t s2u(const void* p) {
    uint32_t a;
    asm("{ .reg .u64 t; cvta.to.shared.u64 t, %1; cvt.u32.u64 %0, t; }" : "=r"(a) : "l"(p));
    return a;
}
__device__ __forceinline__ void cpa16(uint32_t dst, const void* src) {
    asm volatile("cp.async.cg.shared.global [%0], [%1], 16;" :: "r"(dst), "l"(src));
}
#define CP_COMMIT() asm volatile("cp.async.commit_group;" ::: "memory")
#define CP_WAIT2()  asm volatile("cp.async.wait_group 2;" ::: "memory")

// ---- warp-level fp16 HMMA ----
__device__ __forceinline__ void mma16816(float* c, const uint32_t* a, const uint32_t* b) {
    asm volatile(
        "mma.sync.aligned.m16n8k16.row.col.f32.f16.f16.f32 "
        "{%0,%1,%2,%3}, {%4,%5,%6,%7}, {%8,%9}, {%0,%1,%2,%3};"
        : "+f"(c[0]), "+f"(c[1]), "+f"(c[2]), "+f"(c[3])
        : "r"(a[0]), "r"(a[1]), "r"(a[2]), "r"(a[3]), "r"(b[0]), "r"(b[1]));
}

// ====== HMMA GEMM: C[M,N] = A[M,K] @ W[N,K]^T, operands pre-split fp16 hi/lo ======
// 3 MMA passes (hh, lh, hl); dropped ll term error ~2^-22.
// Pure cp.async operand feed: 4-stage smem ring, one commit-group per chunk.
// Grid: (N/64, M/64, splits). Block 256 = 8 warps (4m x 2n), warp tile 16x32. BK=16.
// EPI: 0 plain fp32 store; 2 softplus(+bias); 4 split-K partial -> g_part;
//      6 x_proj special (wn==0 -> dtr hi/lo, wn==1 -> g_proj fp32)
#define SKA 24
template <int EPI>
__global__ void __launch_bounds__(256, 3)
mma_gemm(const __half* __restrict__ Ah, const __half* __restrict__ Al, int lda,
         const __half* __restrict__ Wh, const __half* __restrict__ Wl, int ldb,
         const float* __restrict__ bias, float* __restrict__ C, int ldc, int kSpan)
{
    __shared__ __half sm[4][4][64][SKA];   // [arr: Ah,Al,Wh,Wl][stage][row][k] (48 KB)

    const int tid = threadIdx.x;
    const int wid = tid >> 5, lane = tid & 31;
    const int wm = wid >> 1, wn = wid & 1;
    const int grp = lane >> 2, tq = lane & 3;

    const int m0 = blockIdx.y * 64;
    const int n0 = blockIdx.x * 64;
    const int kBase = blockIdx.z * kSpan;
    const int nChunks = kSpan >> 4;

    // this thread's 2 transfer descriptors (fixed across chunks)
    const __half* bp[2];
    int arrv[2], rrv[2], offv[2];
#pragma unroll
    for (int e = 0; e < 2; e++) {
        const int j = tid * 2 + e;
        const int arr = j >> 7;
        const int rr = (j >> 1) & 63;
        const int off = (j & 1) * 8;
        arrv[e] = arr; rrv[e] = rr; offv[e] = off;
        if (arr == 0)      bp[e] = Ah + (size_t)(m0 + rr) * lda + kBase + off;
        else if (arr == 1) bp[e] = Al + (size_t)(m0 + rr) * lda + kBase + off;
        else if (arr == 2) bp[e] = Wh + (size_t)(n0 + rr) * ldb + kBase + off;
        else               bp[e] = Wl + (size_t)(n0 + rr) * ldb + kBase + off;
    }

    auto issue = [&](int c, int st) {
        if (c < nChunks) {
#pragma unroll
            for (int e = 0; e < 2; e++) {
                uint32_t dst = s2u(&sm[arrv[e]][st][rrv[e]][offv[e]]);
                cpa16(dst, bp[e] + c * 16);
            }
        }
        CP_COMMIT();
    };

    float acc[4][4];
#pragma unroll
    for (int j = 0; j < 4; j++)
#pragma unroll
        for (int q = 0; q < 4; q++) acc[j][q] = 0.f;

    issue(0, 0); issue(1, 1); issue(2, 2);

    for (int c = 0; c < nChunks; c++) {
        const int st = c & 3;
        CP_WAIT2();
        __syncthreads();
        uint32_t Afh[4], Afl[4], Bfh[4][2], Bfl[4][2];
        {
            const int r = wm * 16 + grp;
            Afh[0] = *(const uint32_t*)&sm[0][st][r][2 * tq];
            Afh[1] = *(const uint32_t*)&sm[0][st][r + 8][2 * tq];
            Afh[2] = *(const uint32_t*)&sm[0][st][r][2 * tq + 8];
            Afh[3] = *(const uint32_t*)&sm[0][st][r + 8][2 * tq + 8];
            Afl[0] = *(const uint32_t*)&sm[1][st][r][2 * tq];
            Afl[1] = *(const uint32_t*)&sm[1][st][r + 8][2 * tq];
            Afl[2] = *(const uint32_t*)&sm[1][st][r][2 * tq + 8];
            Afl[3] = *(const uint32_t*)&sm[1][st][r + 8][2 * tq + 8];
        }
#pragma unroll
        for (int nt = 0; nt < 4; nt++) {
            const int col = wn * 32 + nt * 8 + grp;
            Bfh[nt][0] = *(const uint32_t*)&sm[2][st][col][2 * tq];
            Bfh[nt][1] = *(const uint32_t*)&sm[2][st][col][2 * tq + 8];
            Bfl[nt][0] = *(const uint32_t*)&sm[3][st][col][2 * tq];
            Bfl[nt][1] = *(const uint32_t*)&sm[3][st][col][2 * tq + 8];
        }
        issue(c + 3, (c + 3) & 3);
#pragma unroll
        for (int nt = 0; nt < 4; nt++) {
            mma16816(acc[nt], Afh, Bfh[nt]);
            mma16816(acc[nt], Afl, Bfh[nt]);
            mma16816(acc[nt], Afh, Bfl[nt]);
        }
    }

    const int Nt = gridDim.x * 64;
    const int Mt = gridDim.y * 64;
#pragma unroll
    for (int nt = 0; nt < 4; nt++) {
        const int col = n0 + wn * 32 + nt * 8 + 2 * tq;
#pragma unroll
        for (int half = 0; half < 2; half++) {
            const int r = m0 + wm * 16 + grp + half * 8;
            float v0 = acc[nt][half * 2 + 0];
            float v1 = acc[nt][half * 2 + 1];
            if constexpr (EPI == 2) {
                v0 = softplusf(v0 + bias[col]);
                v1 = softplusf(v1 + bias[col + 1]);
            }
            if constexpr (EPI == 6) {
                if (wn == 0) {   // dtr columns 0..31 -> hi/lo halves
                    hsplit(v0, &g_dtrh[r * 32 + col], &g_dtrl[r * 32 + col]);
                    hsplit(v1, &g_dtrh[r * 32 + col + 1], &g_dtrl[r * 32 + col + 1]);
                } else {          // B/C columns 32..63 -> fp32 proj
                    g_proj[r * 64 + col] = v0;
                    g_proj[r * 64 + col + 1] = v1;
                }
            } else if constexpr (EPI == 4) {
                *(float2*)(g_part + (size_t)blockIdx.z * Mt * Nt + (size_t)r * Nt + col)
                    = make_float2(v0, v1);
            } else {
                *(float2*)(C + (size_t)r * ldc + col) = make_float2(v0, v1);
            }
        }
    }
}

// ---------------- weight pre-split ----------------
__global__ void wsplit_kernel(const float* __restrict__ src, __half* __restrict__ dh,
                              __half* __restrict__ dl, int n)
{
    int i = blockIdx.x * 256 + threadIdx.x;
    if (i < n) {
        float v = src[i];
        __half h = __float2half_rn(v);
        dh[i] = h;
        dl[i] = __float2half_rn(v - __half2float(h));
    }
}

__global__ void reduce_bias(float* __restrict__ C, int MN, int ns,
                            const float* __restrict__ bias, int nmask)
{
    int i = blockIdx.x * 256 + threadIdx.x;
    if (i < MN) {
        float s = bias[i & nmask];
        for (int z = 0; z < ns; z++) s += g_part[(size_t)z * MN + i];
        C[i] = s;
    }
}

// ---------------- tokenize ----------------
__global__ void patch_mean_kernel(const float* __restrict__ images)
{
    const int blc = blockIdx.x;
    const int tid = threadIdx.x;
    const int y = tid >> 4, x = tid & 15;
    const int c = blc % 3, bl = blc / 3;
    const float* base = images + (size_t)blc * 224 * 224;
    float s = 0.f;
#pragma unroll 2
    for (int py = 0; py < 14; py++) {
        const float* row = base + (py * 16 + y) * 224 + x;
#pragma unroll
        for (int px = 0; px < 14; px++) s += row[px * 16];
    }
    const int idx = bl * 768 + c * 256 + tid;
    hsplit(s * (1.0f / 196.0f), &g_mph[idx], &g_mpl[idx]);
}

__global__ void token_kernel(const float* __restrict__ states,
                             const float* __restrict__ state_w, const float* __restrict__ state_b,
                             const float* __restrict__ actions,
                             const float* __restrict__ act_w, const float* __restrict__ act_b)
{
    const int bl = blockIdx.x;
    const int d = threadIdx.x;
    const int b = bl >> 6, li = bl & 63;
    const int base = b * SLEN + li * 4;

    g_hidden[(size_t)(base + 0) * DMODEL + d] = g_imgtok[(size_t)bl * DMODEL + d];

    const float* st = states + (size_t)bl * 3 * 7;
    float s = state_b[d];
#pragma unroll
    for (int j = 0; j < 7; j++) s = fmaf(st[j], state_w[d * 7 + j], s);
    g_hidden[(size_t)(base + 1) * DMODEL + d] = s;

#pragma unroll
    for (int t = 0; t < 2; t++) {
        const float* ac = actions + (size_t)(bl * 3 + t) * 4;
        float a = act_b[d];
#pragma unroll
        for (int j = 0; j < 4; j++) a = fmaf(ac[j], act_w[d * 4 + j], a);
        g_hidden[(size_t)(base + 2 + t) * DMODEL + d] = a;
    }
}

__global__ void aneg_kernel(const float* __restrict__ A_log)
{
    int i = blockIdx.x * 256 + threadIdx.x;
    if (i < LNUM * DINX * DSX) g_Aneg[i] = -expf(A_log[i]);
}

// residual += hidden (g_hidden if NS==0 which is also layer-0 zero-resid; else NS partials)
// then xnorm = rms(residual)*w, written fp32 + fp16 hi/lo
template <int NS>
__global__ void add_rms_kernel(const float* __restrict__ w)
{
    const int t = blockIdx.x;
    const int tid = threadIdx.x;      // 256
    const size_t base = (size_t)t * DMODEL;
    float a0, a1;
    if (NS == 0) {
        a0 = g_hidden[base + tid];
        a1 = g_hidden[base + 256 + tid];
    } else {
        a0 = 0.f; a1 = 0.f;
#pragma unroll
        for (int z = 0; z < NS; z++) {
            a0 += g_part[(size_t)z * TTOT * DMODEL + base + tid];
            a1 += g_part[(size_t)z * TTOT * DMODEL + base + 256 + tid];
        }
        a0 += g_resid[base + tid];
        a1 += g_resid[base + 256 + tid];
    }
    g_resid[base + tid] = a0;
    g_resid[base + 256 + tid] = a1;
    float ss = a0 * a0 + a1 * a1;
#pragma unroll
    for (int off = 16; off; off >>= 1) ss += __shfl_xor_sync(0xffffffffu, ss, off);
    __shared__ float red[8];
    if ((tid & 31) == 0) red[tid >> 5] = ss;
    __syncthreads();
    float tot = red[0] + red[1] + red[2] + red[3] + red[4] + red[5] + red[6] + red[7];
    float sc = rsqrtf(tot * (1.0f / 512.0f) + 1e-5f);
    float x0 = a0 * sc * w[tid];
    float x1 = a1 * sc * w[256 + tid];
    g_xnorm[base + tid] = x0;
    g_xnorm[base + 256 + tid] = x1;
    hsplit(x0, &g_xnh[base + tid], &g_xnl[base + tid]);
    hsplit(x1, &g_xnh[base + 256 + tid], &g_xnl[base + 256 + tid]);
}

__global__ void conv_kernel(const float* __restrict__ cw, const float* __restrict__ cb)
{
    int idx = blockIdx.x * 256 + threadIdx.x;
    if (idx >= TTOT * DINX) return;
    const int d = idx & (DINX - 1);
    const int t = idx >> 10;
    const int b = t >> 8, s = t & 255;
    const float* w4 = cw + d * 4;
    float acc = cb[d];
#pragma unroll
    for (int k = 0; k < 4; k++) {
        int ss = s - 3 + k;
        if (ss >= 0) acc = fmaf(w4[k], g_xz[(size_t)(b * SLEN + ss) * 2048 + d], acc);
    }
    float v = siluf(acc);
    g_xc[idx] = v;
    hsplit(v, &g_xch[idx], &g_xcl[idx]);
}

// ---------------- selective scan (smem-tiled, gate fused in epilogue) ----------------
// Grid (64, 2), block 256 = 16 d-channels x 16 states.
__global__ void scan_kernel(int l, const float* __restrict__ Dp_l)
{
    const int b = blockIdx.y;
    const int d0 = blockIdx.x << 4;
    const int tid = threadIdx.x;
    const int d = tid >> 4, n = tid & 15;
    const float Aa = g_Aneg[((size_t)l * DINX + d0 + d) * DSX + n];
    const float Dv = Dp_l[d0 + d];

    __shared__ float sdt[2][32][16], sxc[2][32][16], sBt[2][32][16], sCt[2][32][16],
                     szt[2][32][16];

    float r0[5], r1[5];
    const int ls = tid >> 4, ld = tid & 15;
    auto fetchT = [&](int tile) {
        const int t0 = (b << 8) + (tile << 5);
        r0[0] = g_dt[(size_t)(t0 + ls) * DINX + d0 + ld];
        r0[1] = g_xc[(size_t)(t0 + ls) * DINX + d0 + ld];
        r0[2] = g_proj[(t0 + ls) * 64 + 32 + ld];
        r0[3] = g_proj[(t0 + ls) * 64 + 48 + ld];
        r0[4] = g_xz[(size_t)(t0 + ls) * 2048 + 1024 + d0 + ld];
        r1[0] = g_dt[(size_t)(t0 + 16 + ls) * DINX + d0 + ld];
        r1[1] = g_xc[(size_t)(t0 + 16 + ls) * DINX + d0 + ld];
        r1[2] = g_proj[(t0 + 16 + ls) * 64 + 32 + ld];
        r1[3] = g_proj[(t0 + 16 + ls) * 64 + 48 + ld];
        r1[4] = g_xz[(size_t)(t0 + 16 + ls) * 2048 + 1024 + d0 + ld];
    };
    auto commitT = [&](int buf) {
        sdt[buf][ls][ld] = r0[0]; sxc[buf][ls][ld] = r0[1];
        sBt[buf][ls][ld] = r0[2]; sCt[buf][ls][ld] = r0[3];
        szt[buf][ls][ld] = r0[4];
        sdt[buf][ls + 16][ld] = r1[0]; sxc[buf][ls + 16][ld] = r1[1];
        sBt[buf][ls + 16][ld] = r1[2]; sCt[buf][ls + 16][ld] = r1[3];
        szt[buf][ls + 16][ld] = r1[4];
    };

    fetchT(0); commitT(0);
    fetchT(1);
    __syncthreads();

    float h = 0.f;
    for (int tile = 0; tile < 8; tile++) {
        const int buf = tile & 1;
        const int t0 = (b << 8) + (tile << 5);
#pragma unroll 8
        for (int s = 0; s < 32; s++) {
            float dtv = sdt[buf][s][d];
            float xv  = sxc[buf][s][d];
            float Bn  = sBt[buf][s][n];
            float Cn  = sCt[buf][s][n];
            float a = __expf(dtv * Aa);
            h = fmaf(a, h, dtv * Bn * xv);
            float c = h * Cn;
            c += __shfl_down_sync(0xffffffffu, c, 8, 16);
            c += __shfl_down_sync(0xffffffffu, c, 4, 16);
            c += __shfl_down_sync(0xffffffffu, c, 2, 16);
            c += __shfl_down_sync(0xffffffffu, c, 1, 16);
            if (n == 0) {
                float ym = fmaf(Dv, xv, c) * siluf(szt[buf][s][d]);
                const size_t oi = (size_t)(t0 + s) * DINX + d0 + d;
                hsplit(ym, &g_ymh[oi], &g_yml[oi]);
            }
        }
        __syncthreads();
        if (tile + 1 < 8) {
            commitT((tile + 1) & 1);
            if (tile + 2 < 8) fetchT(tile + 2);
            __syncthreads();
        }
    }
}

__global__ void glu_kernel()
{
    int idx = blockIdx.x * 256 + threadIdx.x;
    if (idx >= TTOT * DINX) return;
    const int d = idx & (DINX - 1);
    const int t = idx >> 10;
    float u = g_g[(size_t)t * 2048 + d] * siluf(g_g[(size_t)t * 2048 + 1024 + d]);
    hsplit(u, &g_uh[idx], &g_ul[idx]);
}

// ---------------- head + loss ----------------
__global__ void head_kernel(const float* __restrict__ head_w, const float* __restrict__ head_b,
                            const float* __restrict__ labels,
                            float* __restrict__ out, int ofs, int write_preds)
{
    const int bl = blockIdx.x;
    const int w = threadIdx.x >> 5;
    const int lane = threadIdx.x & 31;
    const int t = w >> 2, a = w & 3;
    const int b = bl >> 6, li = bl & 63;
    const int tok = b * SLEN + li * 4 + 1 + t;
    const float* x = g_xnorm + (size_t)tok * DMODEL;
    const float* hw = head_w + a * DMODEL;
    float s = 0.f;
    for (int i = lane; i < DMODEL; i += 32) s = fmaf(x[i], hw[i], s);
#pragma unroll
    for (int off = 16; off; off >>= 1) s += __shfl_xor_sync(0xffffffffu, s, off);
    __shared__ float sd[12];
    if (lane == 0) {
        float pred = s + head_b[a];
        int idx = bl * 12 + t * 4 + a;
        if (write_preds) out[ofs + idx] = pred;
        sd[w] = fabsf(pred - labels[idx]);
    }
    __syncthreads();
    if (threadIdx.x == 0) {
        float acc = 0.f;
#pragma unroll
        for (int i = 0; i < 12; i++) acc += sd[i];
        g_la[bl] = acc * (1.0f / 12.0f);
    }
}

__global__ void loss_kernel(const int* __restrict__ seqlen, float* __restrict__ out, int write_loss)
{
    const int tid = threadIdx.x;
    const int b = tid >> 6, li = tid & 63;
    float m = (li < seqlen[b]) ? 1.f : 0.f;
    __shared__ float sv[128], sm[128];
    sv[tid] = g_la[tid] * m;
    sm[tid] = m;
    __syncthreads();
    if (tid == 0 && write_loss) {
        float s0 = 0, c0 = 0, s1 = 0, c1 = 0;
        for (int i = 0; i < 64; i++) { s0 += sv[i]; c0 += sm[i]; s1 += sv[64 + i]; c1 += sm[64 + i]; }
        float l0 = s0 / fmaxf(c0, 1.f);
        float l1 = s1 / fmaxf(c1, 1.f);
        out[0] = 0.5f * (l0 + l1);
    }
}

// ---------------- host ----------------
extern "C" void kernel_launch(void* const* d_in, const int* in_sizes, int n_in,
                              void* d_out, int out_size)
{
    const float* images   = (const float*)d_in[0];
    const int*   seqlen   = (const int*)  d_in[1];
    const float* states   = (const float*)d_in[2];
    const float* actions  = (const float*)d_in[3];
    const float* labels   = (const float*)d_in[4];
    const float* patch_w  = (const float*)d_in[5];
    const float* patch_b  = (const float*)d_in[6];
    const float* state_w  = (const float*)d_in[7];
    const float* state_b  = (const float*)d_in[8];
    const float* act_w    = (const float*)d_in[9];
    const float* act_b    = (const float*)d_in[10];
    const float* norm1_w  = (const float*)d_in[11];
    const float* in_proj_w= (const float*)d_in[12];
    const float* conv_w   = (const float*)d_in[13];
    const float* conv_b   = (const float*)d_in[14];
    const float* x_proj_w = (const float*)d_in[15];
    const float* dt_w     = (const float*)d_in[16];
    const float* dt_b     = (const float*)d_in[17];
    const float* A_log    = (const float*)d_in[18];
    const float* Dp       = (const float*)d_in[19];
    const float* out_proj_w=(const float*)d_in[20];
    const float* norm2_w  = (const float*)d_in[21];
    const float* fc1_w    = (const float*)d_in[22];
    const float* fc2_w    = (const float*)d_in[23];
    const float* norm_f_w = (const float*)d_in[24];
    const float* head_w   = (const float*)d_in[25];
    const float* head_b   = (const float*)d_in[26];
    float* out = (float*)d_out;

    __half *p_wh, *p_wl, *p_mph, *p_mpl, *p_xnh, *p_xnl, *p_xch, *p_xcl;
    __half *p_dtrh, *p_dtrl, *p_ymh, *p_yml, *p_uh, *p_ul;
    float *p_imgtok, *p_xz, *p_dt, *p_g;
    cudaGetSymbolAddress((void**)&p_wh, g_wh);
    cudaGetSymbolAddress((void**)&p_wl, g_wl);
    cudaGetSymbolAddress((void**)&p_mph, g_mph);
    cudaGetSymbolAddress((void**)&p_mpl, g_mpl);
    cudaGetSymbolAddress((void**)&p_xnh, g_xnh);
    cudaGetSymbolAddress((void**)&p_xnl, g_xnl);
    cudaGetSymbolAddress((void**)&p_xch, g_xch);
    cudaGetSymbolAddress((void**)&p_xcl, g_xcl);
    cudaGetSymbolAddress((void**)&p_dtrh, g_dtrh);
    cudaGetSymbolAddress((void**)&p_dtrl, g_dtrl);
    cudaGetSymbolAddress((void**)&p_ymh, g_ymh);
    cudaGetSymbolAddress((void**)&p_yml, g_yml);
    cudaGetSymbolAddress((void**)&p_uh, g_uh);
    cudaGetSymbolAddress((void**)&p_ul, g_ul);
    cudaGetSymbolAddress((void**)&p_imgtok, g_imgtok);
    cudaGetSymbolAddress((void**)&p_xz, g_xz);
    cudaGetSymbolAddress((void**)&p_dt, g_dt);
    cudaGetSymbolAddress((void**)&p_g, g_g);

    // ---- weight pre-split (all layers batched per tensor) ----
    auto wsp = [&](const float* src, size_t off, int n) {
        wsplit_kernel<<<(n + 255) / 256, 256>>>(src, p_wh + off, p_wl + off, n);
    };
    wsp(patch_w,    OFF_PATCH, 512 * 768);
    wsp(in_proj_w,  OFF_INPJ,  LNUM * 2048 * 512);
    wsp(x_proj_w,   OFF_XPJ,   LNUM * 64 * 1024);
    wsp(dt_w,       OFF_DTW,   LNUM * 1024 * 32);
    wsp(out_proj_w, OFF_OUTP,  LNUM * 512 * 1024);
    wsp(fc1_w,      OFF_FC1,   LNUM * 2048 * 512);
    wsp(fc2_w,      OFF_FC2,   LNUM * 512 * 1024);

    aneg_kernel<<<(LNUM * DINX * DSX + 255) / 256, 256>>>(A_log);
    patch_mean_kernel<<<384, 256>>>(images);
    // img tokens: [128,512] = meanp @ patch_w^T + patch_b (split-K 4)
    mma_gemm<4><<<dim3(8, 2, 4), 256>>>(p_mph, p_mpl, 768,
        p_wh + OFF_PATCH, p_wl + OFF_PATCH, 768, nullptr, nullptr, 512, 192);
    reduce_bias<<<(128 * 512 + 255) / 256, 256>>>(p_imgtok, 128 * 512, 4, patch_b, 511);
    token_kernel<<<128, 512>>>(states, state_w, state_b, actions, act_w, act_b);

    for (int l = 0; l < LNUM; l++) {
        if (l == 0) add_rms_kernel<0><<<TTOT, 256>>>(norm1_w);
        else        add_rms_kernel<4><<<TTOT, 256>>>(norm1_w + l * DMODEL);
        // xz[512,2048] = xnorm @ in_proj^T
        mma_gemm<0><<<dim3(32, 8, 1), 256>>>(p_xnh, p_xnl, 512,
            p_wh + OFF_INPJ + (size_t)l * 1048576, p_wl + OFF_INPJ + (size_t)l * 1048576,
            512, nullptr, p_xz, 2048, 512);
        conv_kernel<<<(TTOT * DINX + 255) / 256, 256>>>(conv_w + (size_t)l * DINX * 4,
                                                        conv_b + l * DINX);
        // proj[512,64] = xc @ x_proj^T; epilogue splits dtr (cols<32) + proj fp32
        mma_gemm<6><<<dim3(1, 8, 1), 256>>>(p_xch, p_xcl, 1024,
            p_wh + OFF_XPJ + (size_t)l * 65536, p_wl + OFF_XPJ + (size_t)l * 65536,
            1024, nullptr, nullptr, 64, 1024);
        // dt[512,1024] = softplus(dtr @ dt_w^T + dt_b)
        mma_gemm<2><<<dim3(16, 8, 1), 256>>>(p_dtrh, p_dtrl, 32,
            p_wh + OFF_DTW + (size_t)l * 32768, p_wl + OFF_DTW + (size_t)l * 32768,
            32, dt_b + l * DINX, p_dt, 1024, 32);
        scan_kernel<<<dim3(64, 2), 256>>>(l, Dp + l * DINX);
        // hidden_partials = ym @ out_proj^T (split-K 4)
        mma_gemm<4><<<dim3(8, 8, 4), 256>>>(p_ymh, p_yml, 1024,
            p_wh + OFF_OUTP + (size_t)l * 524288, p_wl + OFF_OUTP + (size_t)l * 524288,
            1024, nullptr, nullptr, 512, 256);
        add_rms_kernel<4><<<TTOT, 256>>>(norm2_w + l * DMODEL);
        // g[512,2048] = xnorm @ fc1^T
        mma_gemm<0><<<dim3(32, 8, 1), 256>>>(p_xnh, p_xnl, 512,
            p_wh + OFF_FC1 + (size_t)l * 1048576, p_wl + OFF_FC1 + (size_t)l * 1048576,
            512, nullptr, p_g, 2048, 512);
        glu_kernel<<<(TTOT * DINX + 255) / 256, 256>>>();
        // hidden_partials = u @ fc2^T (split-K 4)
        mma_gemm<4><<<dim3(8, 8, 4), 256>>>(p_uh, p_ul, 1024,
            p_wh + OFF_FC2 + (size_t)l * 524288, p_wl + OFF_FC2 + (size_t)l * 524288,
            1024, nullptr, nullptr, 512, 256);
    }

    // final norm + head + loss
    add_rms_kernel<4><<<TTOT, 256>>>(norm_f_w);
    int write_preds = (out_size >= 1536) ? 1 : 0;
    int ofs = (out_size == 1536) ? 0 : 1;
    int write_loss = (out_size != 1536) ? 1 : 0;
    head_kernel<<<128, 384>>>(head_w, head_b, labels, out, ofs, write_preds);
    loss_kernel<<<1, 128>>>(seqlen, out, write_loss);
}

// round 11
// speedup vs baseline: 1.5142x; 1.5142x over previous
#include <cuda_runtime.h>
#include <cuda_fp16.h>
#include <math.h>
#include <stdint.h>

#define LNUM 8
#define DMODEL 512
#define DINX 1024
#define DSX 16
#define SLEN 256
#define TTOT 512   // BATCH * SLEN tokens

// ---------------- scratch (static device memory; no allocations) ----------------
__device__ float g_meanp[128 * 768];
__device__ float g_imgtok[128 * DMODEL];
__device__ float g_hidden[TTOT * DMODEL];
__device__ float g_resid[TTOT * DMODEL];
__device__ float g_xnorm[TTOT * DMODEL];
__device__ float g_xz[TTOT * 2 * DINX];
__device__ float g_xc[TTOT * DINX];
__device__ float g_proj[TTOT * 64];
__device__ float g_dt[TTOT * DINX];
__device__ float g_y[TTOT * DINX];
__device__ float g_g[TTOT * 2 * DINX];
__device__ float g_Aneg[LNUM * DINX * DSX];
__device__ float g_part[4 * TTOT * DMODEL];   // split-K partial slab (4 MB)
__device__ float g_la[128];

__device__ __forceinline__ float siluf(float x) { return x / (1.0f + __expf(-x)); }
__device__ __forceinline__ float softplusf(float x) {
    return fmaxf(x, 0.0f) + log1pf(__expf(-fabsf(x)));
}

// ---- warp-level fp16 HMMA (sm_80+ PTX; tensor-core path that compiles for sm_103) ----
__device__ __forceinline__ void mma16816(float* c, const uint32_t* a, const uint32_t* b) {
    asm volatile(
        "mma.sync.aligned.m16n8k16.row.col.f32.f16.f16.f32 "
        "{%0,%1,%2,%3}, {%4,%5,%6,%7}, {%8,%9}, {%0,%1,%2,%3};"
        : "+f"(c[0]), "+f"(c[1]), "+f"(c[2]), "+f"(c[3])
        : "r"(a[0]), "r"(a[1]), "r"(a[2]), "r"(a[3]), "r"(b[0]), "r"(b[1]));
}

// ====== HMMA GEMM: C[M,N] = A[M,K] @ W[N,K]^T ======
// fp32 accuracy via fp16 hi/lo split of BOTH operands; 3 MMA passes (hh, lh, hl),
// dropped ll term error ~2^-22.
// Grid: (N/64, M/64, splits). Block 256 = 8 warps (4m x 2n), warp tile 16x32.
// BK = 32 (one barrier per 24 MMAs), double-buffered DYNAMIC smem (80 KB),
// register double-buffer with one-iteration LDG->consume distance.
// AOP: 0 = A[m*lda+k]; 1 = gate y*silu(z); 2 = glu g1*silu(g2)
// EPI: 0 plain store (ldc), 2 softplus(+bias), 4 split-K partial -> g_part
#define SKB 40   // padded row stride (halves) for BK=32: conflict-free frag LDS
#define GSMEM (4 * 2 * 64 * SKB * 2)   // 4 arrays x 2 buffers x 64 rows x 40 halves = 81920 B

template <int AOP, int EPI>
__global__ void __launch_bounds__(256, 2)
mma_gemm(const float* __restrict__ A, int lda,
         const float* __restrict__ W, int ldb,
         const float* __restrict__ bias,
         float* __restrict__ C, int ldc, int kSpan)
{
    extern __shared__ __half smh[];
    // array ids: 0=Ah, 1=Al, 2=Bh, 3=Bl
    auto sp = [&](int arr, int buf, int row, int k) -> __half* {
        return smh + ((size_t)((arr * 2 + buf) * 64 + row)) * SKB + k;
    };

    const int tid = threadIdx.x;
    const int wid = tid >> 5, lane = tid & 31;
    const int wm = wid >> 1, wn = wid & 1;       // 4 m-tiles x 2 n-tiles
    const int grp = lane >> 2, tq = lane & 3;

    const int m0 = blockIdx.y * 64;
    const int n0 = blockIdx.x * 64;
    const int kBase = blockIdx.z * kSpan;
    const int nChunks = kSpan >> 5;              // BK = 32

    float acc[4][4];
#pragma unroll
    for (int j = 0; j < 4; j++)
#pragma unroll
        for (int q = 0; q < 4; q++) acc[j][q] = 0.f;

    const int row = tid >> 2;     // 0..63
    const int kq = (tid & 3) * 8; // 0,8,16,24 (this thread covers k kq..kq+7)

    auto loadA = [&](int m, int k) -> float4 {
        if constexpr (AOP == 0) {
            return *(const float4*)(A + (size_t)m * lda + k);
        } else if constexpr (AOP == 1) {
            float4 y = *(const float4*)(g_y + (size_t)m * DINX + k);
            float4 z = *(const float4*)(g_xz + (size_t)m * 2048 + 1024 + k);
            return make_float4(y.x * siluf(z.x), y.y * siluf(z.y),
                               y.z * siluf(z.z), y.w * siluf(z.w));
        } else {
            float4 a = *(const float4*)(g_g + (size_t)m * 2048 + k);
            float4 b = *(const float4*)(g_g + (size_t)m * 2048 + 1024 + k);
            return make_float4(a.x * siluf(b.x), a.y * siluf(b.y),
                               a.z * siluf(b.z), a.w * siluf(b.w));
        }
    };

    float4 rgA[2], rgB[2];        // one chunk in flight
    auto fetch = [&](int c) {
        const int k = kBase + c * 32 + kq;
        rgA[0] = loadA(m0 + row, k);
        rgA[1] = loadA(m0 + row, k + 4);
        rgB[0] = *(const float4*)(W + (size_t)(n0 + row) * ldb + k);
        rgB[1] = *(const float4*)(W + (size_t)(n0 + row) * ldb + k + 4);
    };
    auto split8 = [&](const float4* v2, int arrH, int arrL, int buf) {
#pragma unroll
        for (int i = 0; i < 2; i++) {
            const float4 v = v2[i];
            const float vv[4] = {v.x, v.y, v.z, v.w};
            union { __half h[4]; uint2 u; } H, L;
#pragma unroll
            for (int q = 0; q < 4; q++) {
                __half h = __float2half_rn(vv[q]);
                H.h[q] = h;
                L.h[q] = __float2half_rn(vv[q] - __half2float(h));
            }
            *(uint2*)sp(arrH, buf, row, kq + i * 4) = H.u;
            *(uint2*)sp(arrL, buf, row, kq + i * 4) = L.u;
        }
    };
    auto store = [&](int buf) {
        split8(rgA, 0, 1, buf);
        split8(rgB, 2, 3, buf);
    };

    fetch(0);
    store(0);
    if (nChunks > 1) fetch(1);
    __syncthreads();

    for (int c = 0; c < nChunks; c++) {
        const int buf = c & 1;
        // stage chunk c+1 (fetched last iteration) into the other buffer, then
        // issue LDG for chunk c+2 (consumed one full iteration from now)
        if (c + 1 < nChunks) {
            store(buf ^ 1);
            if (c + 2 < nChunks) fetch(c + 2);
        }
        // two K16 steps per chunk, one barrier total
#pragma unroll
        for (int ks = 0; ks < 2; ks++) {
            const int ko = ks * 16;
            uint32_t Ah[4], Al[4], Bh[4][2], Bl[4][2];
            {
                const int r = wm * 16 + grp;
                Ah[0] = *(const uint32_t*)sp(0, buf, r,     ko + 2 * tq);
                Ah[1] = *(const uint32_t*)sp(0, buf, r + 8, ko + 2 * tq);
                Ah[2] = *(const uint32_t*)sp(0, buf, r,     ko + 2 * tq + 8);
                Ah[3] = *(const uint32_t*)sp(0, buf, r + 8, ko + 2 * tq + 8);
                Al[0] = *(const uint32_t*)sp(1, buf, r,     ko + 2 * tq);
                Al[1] = *(const uint32_t*)sp(1, buf, r + 8, ko + 2 * tq);
                Al[2] = *(const uint32_t*)sp(1, buf, r,     ko + 2 * tq + 8);
                Al[3] = *(const uint32_t*)sp(1, buf, r + 8, ko + 2 * tq + 8);
            }
#pragma unroll
            for (int nt = 0; nt < 4; nt++) {
                const int col = wn * 32 + nt * 8 + grp;
                Bh[nt][0] = *(const uint32_t*)sp(2, buf, col, ko + 2 * tq);
                Bh[nt][1] = *(const uint32_t*)sp(2, buf, col, ko + 2 * tq + 8);
                Bl[nt][0] = *(const uint32_t*)sp(3, buf, col, ko + 2 * tq);
                Bl[nt][1] = *(const uint32_t*)sp(3, buf, col, ko + 2 * tq + 8);
            }
#pragma unroll
            for (int nt = 0; nt < 4; nt++) {
                mma16816(acc[nt], Ah, Bh[nt]);
                mma16816(acc[nt], Al, Bh[nt]);
                mma16816(acc[nt], Ah, Bl[nt]);
            }
        }
        __syncthreads();
    }

    const int Nt = gridDim.x * 64;
    const int Mt = gridDim.y * 64;
#pragma unroll
    for (int nt = 0; nt < 4; nt++) {
        const int col = n0 + wn * 32 + nt * 8 + 2 * tq;
#pragma unroll
        for (int half = 0; half < 2; half++) {
            const int r = m0 + wm * 16 + grp + half * 8;
            float v0 = acc[nt][half * 2 + 0];
            float v1 = acc[nt][half * 2 + 1];
            if constexpr (EPI == 2) {
                v0 = softplusf(v0 + bias[col]);
                v1 = softplusf(v1 + bias[col + 1]);
            }
            float2 v = make_float2(v0, v1);
            if constexpr (EPI == 4) {
                *(float2*)(g_part + (size_t)blockIdx.z * Mt * Nt + (size_t)r * Nt + col) = v;
            } else {
                *(float2*)(C + (size_t)r * ldc + col) = v;
            }
        }
    }
}

__global__ void reduce_part(float* __restrict__ C, int MN, int ns)
{
    int i = blockIdx.x * 256 + threadIdx.x;
    if (i < MN) {
        float s = 0.f;
        for (int z = 0; z < ns; z++) s += g_part[(size_t)z * MN + i];
        C[i] = s;
    }
}

__global__ void reduce_bias(float* __restrict__ C, int MN, int ns,
                            const float* __restrict__ bias, int nmask)
{
    int i = blockIdx.x * 256 + threadIdx.x;
    if (i < MN) {
        float s = bias[i & nmask];
        for (int z = 0; z < ns; z++) s += g_part[(size_t)z * MN + i];
        C[i] = s;
    }
}

// ---------------- tokenize ----------------
__global__ void patch_mean_kernel(const float* __restrict__ images)
{
    const int blc = blockIdx.x;
    const int tid = threadIdx.x;
    const int y = tid >> 4, x = tid & 15;
    const int c = blc % 3, bl = blc / 3;
    const float* base = images + (size_t)blc * 224 * 224;
    float s = 0.f;
#pragma unroll 2
    for (int py = 0; py < 14; py++) {
        const float* row = base + (py * 16 + y) * 224 + x;
#pragma unroll
        for (int px = 0; px < 14; px++) s += row[px * 16];
    }
    g_meanp[(size_t)bl * 768 + c * 256 + tid] = s * (1.0f / 196.0f);
}

__global__ void token_kernel(const float* __restrict__ states,
                             const float* __restrict__ state_w, const float* __restrict__ state_b,
                             const float* __restrict__ actions,
                             const float* __restrict__ act_w, const float* __restrict__ act_b)
{
    const int bl = blockIdx.x;
    const int d = threadIdx.x;
    const int b = bl >> 6, li = bl & 63;
    const int base = b * SLEN + li * 4;

    g_hidden[(size_t)(base + 0) * DMODEL + d] = g_imgtok[(size_t)bl * DMODEL + d];

    const float* st = states + (size_t)bl * 3 * 7;
    float s = state_b[d];
#pragma unroll
    for (int j = 0; j < 7; j++) s = fmaf(st[j], state_w[d * 7 + j], s);
    g_hidden[(size_t)(base + 1) * DMODEL + d] = s;

#pragma unroll
    for (int t = 0; t < 2; t++) {
        const float* ac = actions + (size_t)(bl * 3 + t) * 4;
        float a = act_b[d];
#pragma unroll
        for (int j = 0; j < 4; j++) a = fmaf(ac[j], act_w[d * 4 + j], a);
        g_hidden[(size_t)(base + 2 + t) * DMODEL + d] = a;
    }
}

__global__ void aneg_kernel(const float* __restrict__ A_log)
{
    int i = blockIdx.x * 256 + threadIdx.x;
    if (i < LNUM * DINX * DSX) g_Aneg[i] = -expf(A_log[i]);
}

// residual += hidden (g_hidden if NS==0 which is also layer-0 zero-resid; else NS partials)
template <int NS>
__global__ void add_rms_kernel(const float* __restrict__ w)
{
    const int t = blockIdx.x;
    const int tid = threadIdx.x;      // 256
    const size_t base = (size_t)t * DMODEL;
    float a0, a1;
    if (NS == 0) {
        a0 = g_hidden[base + tid];
        a1 = g_hidden[base + 256 + tid];
    } else {
        a0 = 0.f; a1 = 0.f;
#pragma unroll
        for (int z = 0; z < NS; z++) {
            a0 += g_part[(size_t)z * TTOT * DMODEL + base + tid];
            a1 += g_part[(size_t)z * TTOT * DMODEL + base + 256 + tid];
        }
        a0 += g_resid[base + tid];
        a1 += g_resid[base + 256 + tid];
    }
    g_resid[base + tid] = a0;
    g_resid[base + 256 + tid] = a1;
    float ss = a0 * a0 + a1 * a1;
#pragma unroll
    for (int off = 16; off; off >>= 1) ss += __shfl_xor_sync(0xffffffffu, ss, off);
    __shared__ float red[8];
    if ((tid & 31) == 0) red[tid >> 5] = ss;
    __syncthreads();
    float tot = red[0] + red[1] + red[2] + red[3] + red[4] + red[5] + red[6] + red[7];
    float sc = rsqrtf(tot * (1.0f / 512.0f) + 1e-5f);
    g_xnorm[base + tid] = a0 * sc * w[tid];
    g_xnorm[base + 256 + tid] = a1 * sc * w[256 + tid];
}

__global__ void conv_kernel(const float* __restrict__ cw, const float* __restrict__ cb)
{
    int idx = blockIdx.x * 256 + threadIdx.x;
    if (idx >= TTOT * DINX) return;
    const int d = idx & (DINX - 1);
    const int t = idx >> 10;
    const int b = t >> 8, s = t & 255;
    const float* w4 = cw + d * 4;
    float acc = cb[d];
#pragma unroll
    for (int k = 0; k < 4; k++) {
        int ss = s - 3 + k;
        if (ss >= 0) acc = fmaf(w4[k], g_xz[(size_t)(b * SLEN + ss) * 2048 + d], acc);
    }
    g_xc[idx] = siluf(acc);
}

// ---------------- selective scan (smem-tiled, double-buffered) ----------------
// Grid (64, 2), block 256 = 16 d-channels x 16 states.
__global__ void scan_kernel(int l, const float* __restrict__ Dp_l)
{
    const int b = blockIdx.y;
    const int d0 = blockIdx.x << 4;
    const int tid = threadIdx.x;
    const int d = tid >> 4, n = tid & 15;
    const float Aa = g_Aneg[((size_t)l * DINX + d0 + d) * DSX + n];
    const float Dv = Dp_l[d0 + d];

    __shared__ float sdt[2][32][16], sxc[2][32][16], sBt[2][32][16], sCt[2][32][16];

    float r0[4], r1[4];
    const int ls = tid >> 4, ld = tid & 15;
    auto fetchT = [&](int tile) {
        const int t0 = (b << 8) + (tile << 5);
        r0[0] = g_dt[(size_t)(t0 + ls) * DINX + d0 + ld];
        r0[1] = g_xc[(size_t)(t0 + ls) * DINX + d0 + ld];
        r0[2] = g_proj[(t0 + ls) * 64 + 32 + ld];
        r0[3] = g_proj[(t0 + ls) * 64 + 48 + ld];
        r1[0] = g_dt[(size_t)(t0 + 16 + ls) * DINX + d0 + ld];
        r1[1] = g_xc[(size_t)(t0 + 16 + ls) * DINX + d0 + ld];
        r1[2] = g_proj[(t0 + 16 + ls) * 64 + 32 + ld];
        r1[3] = g_proj[(t0 + 16 + ls) * 64 + 48 + ld];
    };
    auto commitT = [&](int buf) {
        sdt[buf][ls][ld] = r0[0]; sxc[buf][ls][ld] = r0[1];
        sBt[buf][ls][ld] = r0[2]; sCt[buf][ls][ld] = r0[3];
        sdt[buf][ls + 16][ld] = r1[0]; sxc[buf][ls + 16][ld] = r1[1];
        sBt[buf][ls + 16][ld] = r1[2]; sCt[buf][ls + 16][ld] = r1[3];
    };

    fetchT(0); commitT(0);
    fetchT(1);
    __syncthreads();

    float h = 0.f;
    for (int tile = 0; tile < 8; tile++) {
        const int buf = tile & 1;
        const int t0 = (b << 8) + (tile << 5);
#pragma unroll 8
        for (int s = 0; s < 32; s++) {
            float dtv = sdt[buf][s][d];
            float xv  = sxc[buf][s][d];
            float Bn  = sBt[buf][s][n];
            float Cn  = sCt[buf][s][n];
            float a = __expf(dtv * Aa);
            h = fmaf(a, h, dtv * Bn * xv);
            float c = h * Cn;
            c += __shfl_down_sync(0xffffffffu, c, 8, 16);
            c += __shfl_down_sync(0xffffffffu, c, 4, 16);
            c += __shfl_down_sync(0xffffffffu, c, 2, 16);
            c += __shfl_down_sync(0xffffffffu, c, 1, 16);
            if (n == 0) g_y[(size_t)(t0 + s) * DINX + d0 + d] = fmaf(Dv, xv, c);
        }
        __syncthreads();
        if (tile + 1 < 8) {
            commitT((tile + 1) & 1);
            if (tile + 2 < 8) fetchT(tile + 2);
            __syncthreads();
        }
    }
}

// ---------------- head + loss ----------------
__global__ void head_kernel(const float* __restrict__ head_w, const float* __restrict__ head_b,
                            const float* __restrict__ labels,
                            float* __restrict__ out, int ofs, int write_preds)
{
    const int bl = blockIdx.x;
    const int w = threadIdx.x >> 5;
    const int lane = threadIdx.x & 31;
    const int t = w >> 2, a = w & 3;
    const int b = bl >> 6, li = bl & 63;
    const int tok = b * SLEN + li * 4 + 1 + t;
    const float* x = g_xnorm + (size_t)tok * DMODEL;
    const float* hw = head_w + a * DMODEL;
    float s = 0.f;
    for (int i = lane; i < DMODEL; i += 32) s = fmaf(x[i], hw[i], s);
#pragma unroll
    for (int off = 16; off; off >>= 1) s += __shfl_xor_sync(0xffffffffu, s, off);
    __shared__ float sd[12];
    if (lane == 0) {
        float pred = s + head_b[a];
        int idx = bl * 12 + t * 4 + a;
        if (write_preds) out[ofs + idx] = pred;
        sd[w] = fabsf(pred - labels[idx]);
    }
    __syncthreads();
    if (threadIdx.x == 0) {
        float acc = 0.f;
#pragma unroll
        for (int i = 0; i < 12; i++) acc += sd[i];
        g_la[bl] = acc * (1.0f / 12.0f);
    }
}

__global__ void loss_kernel(const int* __restrict__ seqlen, float* __restrict__ out, int write_loss)
{
    const int tid = threadIdx.x;
    const int b = tid >> 6, li = tid & 63;
    float m = (li < seqlen[b]) ? 1.f : 0.f;
    __shared__ float sv[128], sm[128];
    sv[tid] = g_la[tid] * m;
    sm[tid] = m;
    __syncthreads();
    if (tid == 0 && write_loss) {
        float s0 = 0, c0 = 0, s1 = 0, c1 = 0;
        for (int i = 0; i < 64; i++) { s0 += sv[i]; c0 += sm[i]; s1 += sv[64 + i]; c1 += sm[64 + i]; }
        float l0 = s0 / fmaxf(c0, 1.f);
        float l1 = s1 / fmaxf(c1, 1.f);
        out[0] = 0.5f * (l0 + l1);
    }
}

// ---------------- host ----------------
extern "C" void kernel_launch(void* const* d_in, const int* in_sizes, int n_in,
                              void* d_out, int out_size)
{
    const float* images   = (const float*)d_in[0];
    const int*   seqlen   = (const int*)  d_in[1];
    const float* states   = (const float*)d_in[2];
    const float* actions  = (const float*)d_in[3];
    const float* labels   = (const float*)d_in[4];
    const float* patch_w  = (const float*)d_in[5];
    const float* patch_b  = (const float*)d_in[6];
    const float* state_w  = (const float*)d_in[7];
    const float* state_b  = (const float*)d_in[8];
    const float* act_w    = (const float*)d_in[9];
    const float* act_b    = (const float*)d_in[10];
    const float* norm1_w  = (const float*)d_in[11];
    const float* in_proj_w= (const float*)d_in[12];
    const float* conv_w   = (const float*)d_in[13];
    const float* conv_b   = (const float*)d_in[14];
    const float* x_proj_w = (const float*)d_in[15];
    const float* dt_w     = (const float*)d_in[16];
    const float* dt_b     = (const float*)d_in[17];
    const float* A_log    = (const float*)d_in[18];
    const float* Dp       = (const float*)d_in[19];
    const float* out_proj_w=(const float*)d_in[20];
    const float* norm2_w  = (const float*)d_in[21];
    const float* fc1_w    = (const float*)d_in[22];
    const float* fc2_w    = (const float*)d_in[23];
    const float* norm_f_w = (const float*)d_in[24];
    const float* head_w   = (const float*)d_in[25];
    const float* head_b   = (const float*)d_in[26];
    float* out = (float*)d_out;

    float *p_meanp, *p_imgtok, *p_xnorm, *p_xz, *p_xc, *p_proj, *p_dt, *p_g;
    cudaGetSymbolAddress((void**)&p_meanp, g_meanp);
    cudaGetSymbolAddress((void**)&p_imgtok, g_imgtok);
    cudaGetSymbolAddress((void**)&p_xnorm, g_xnorm);
    cudaGetSymbolAddress((void**)&p_xz, g_xz);
    cudaGetSymbolAddress((void**)&p_xc, g_xc);
    cudaGetSymbolAddress((void**)&p_proj, g_proj);
    cudaGetSymbolAddress((void**)&p_dt, g_dt);
    cudaGetSymbolAddress((void**)&p_g, g_g);

    // allow 80 KB dynamic smem on every GEMM instantiation (idempotent)
    cudaFuncSetAttribute(mma_gemm<0,0>, cudaFuncAttributeMaxDynamicSharedMemorySize, GSMEM);
    cudaFuncSetAttribute(mma_gemm<0,2>, cudaFuncAttributeMaxDynamicSharedMemorySize, GSMEM);
    cudaFuncSetAttribute(mma_gemm<0,4>, cudaFuncAttributeMaxDynamicSharedMemorySize, GSMEM);
    cudaFuncSetAttribute(mma_gemm<1,4>, cudaFuncAttributeMaxDynamicSharedMemorySize, GSMEM);
    cudaFuncSetAttribute(mma_gemm<2,4>, cudaFuncAttributeMaxDynamicSharedMemorySize, GSMEM);

    // prologue
    aneg_kernel<<<(LNUM * DINX * DSX + 255) / 256, 256>>>(A_log);
    patch_mean_kernel<<<384, 256>>>(images);
    // img tokens: [128,512] = meanp[128,768] @ patch_w^T + patch_b  (split-K 4)
    mma_gemm<0,4><<<dim3(8, 2, 4), 256, GSMEM>>>(p_meanp, 768, patch_w, 768,
                                                 nullptr, nullptr, 512, 192);
    reduce_bias<<<(128 * 512 + 255) / 256, 256>>>(p_imgtok, 128 * 512, 4, patch_b, 511);
    token_kernel<<<128, 512>>>(states, state_w, state_b, actions, act_w, act_b);

    for (int l = 0; l < LNUM; l++) {
        if (l == 0) add_rms_kernel<0><<<TTOT, 256>>>(norm1_w);
        else        add_rms_kernel<4><<<TTOT, 256>>>(norm1_w + l * DMODEL);
        // xz[512,2048] = xnorm @ in_proj^T (K=512)
        mma_gemm<0,0><<<dim3(32, 8, 1), 256, GSMEM>>>(p_xnorm, 512,
            in_proj_w + (size_t)l * 2048 * 512, 512, nullptr, p_xz, 2048, 512);
        conv_kernel<<<(TTOT * DINX + 255) / 256, 256>>>(conv_w + (size_t)l * DINX * 4,
                                                        conv_b + l * DINX);
        // proj[512,64] = xc @ x_proj^T (K=1024, split-K 8)
        mma_gemm<0,4><<<dim3(1, 8, 8), 256, GSMEM>>>(p_xc, 1024,
            x_proj_w + (size_t)l * 64 * 1024, 1024, nullptr, nullptr, 64, 128);
        reduce_part<<<(TTOT * 64 + 255) / 256, 256>>>(p_proj, TTOT * 64, 8);
        // dt[512,1024] = softplus(dtr @ dt_w^T + dt_b); dtr = proj[:, :32] (lda=64)
        mma_gemm<0,2><<<dim3(16, 8, 1), 256, GSMEM>>>(p_proj, 64,
            dt_w + (size_t)l * 1024 * 32, 32, dt_b + l * DINX, p_dt, 1024, 32);
        scan_kernel<<<dim3(64, 2), 256>>>(l, Dp + l * DINX);
        // hidden_partials = (y*silu(z)) @ out_proj^T (K=1024, split-K 4, gate fused in A)
        mma_gemm<1,4><<<dim3(8, 8, 4), 256, GSMEM>>>(nullptr, 0,
            out_proj_w + (size_t)l * 512 * 1024, 1024, nullptr, nullptr, 512, 256);
        add_rms_kernel<4><<<TTOT, 256>>>(norm2_w + l * DMODEL);
        // g[512,2048] = xnorm @ fc1^T (K=512)
        mma_gemm<0,0><<<dim3(32, 8, 1), 256, GSMEM>>>(p_xnorm, 512,
            fc1_w + (size_t)l * 2048 * 512, 512, nullptr, p_g, 2048, 512);
        // hidden_partials = (g1*silu(g2)) @ fc2^T (K=1024, split-K 4, GLU fused in A)
        mma_gemm<2,4><<<dim3(8, 8, 4), 256, GSMEM>>>(nullptr, 0,
            fc2_w + (size_t)l * 512 * 1024, 1024, nullptr, nullptr, 512, 256);
    }

    // final norm + head + loss
    add_rms_kernel<4><<<TTOT, 256>>>(norm_f_w);
    int write_preds = (out_size >= 1536) ? 1 : 0;
    int ofs = (out_size == 1536) ? 0 : 1;
    int write_loss = (out_size != 1536) ? 1 : 0;
    head_kernel<<<128, 384>>>(head_w, head_b, labels, out, ofs, write_preds);
    loss_kernel<<<1, 128>>>(seqlen, out, write_loss);
}

// round 12
// speedup vs baseline: 1.5983x; 1.0555x over previous
#include <cuda_runtime.h>
#include <cuda_fp16.h>
#include <math.h>
#include <stdint.h>

#define LNUM 8
#define DMODEL 512
#define DINX 1024
#define DSX 16
#define SLEN 256
#define TTOT 512   // BATCH * SLEN tokens

// ---------------- scratch (static device memory; no allocations) ----------------
__device__ float g_meanp[128 * 768];
__device__ float g_imgtok[128 * DMODEL];
__device__ float g_hidden[TTOT * DMODEL];
__device__ float g_resid[TTOT * DMODEL];
__device__ float g_xnorm[TTOT * DMODEL];
__device__ float g_xz[TTOT * 2 * DINX];
__device__ float g_xc[TTOT * DINX];
__device__ float g_proj[TTOT * 64];
__device__ float g_dt[TTOT * DINX];
__device__ float g_y[TTOT * DINX];
__device__ float g_g[TTOT * 2 * DINX];
__device__ float g_Aneg[LNUM * DINX * DSX];
__device__ float g_part[4 * TTOT * DMODEL];   // split-K partial slab (4 MB)
__device__ float g_la[128];

__device__ __forceinline__ float siluf(float x) { return x / (1.0f + __expf(-x)); }
__device__ __forceinline__ float softplusf(float x) {
    return fmaxf(x, 0.0f) + log1pf(__expf(-fabsf(x)));
}

// ---- warp-level fp16 HMMA (sm_80+ PTX; tensor-core path that compiles for sm_103) ----
__device__ __forceinline__ void mma16816(float* c, const uint32_t* a, const uint32_t* b) {
    asm volatile(
        "mma.sync.aligned.m16n8k16.row.col.f32.f16.f16.f32 "
        "{%0,%1,%2,%3}, {%4,%5,%6,%7}, {%8,%9}, {%0,%1,%2,%3};"
        : "+f"(c[0]), "+f"(c[1]), "+f"(c[2]), "+f"(c[3])
        : "r"(a[0]), "r"(a[1]), "r"(a[2]), "r"(a[3]), "r"(b[0]), "r"(b[1]));
}

// ldmatrix x4: 4 8x8 b16 tiles in one instruction (lane i supplies row-address i per tile)
__device__ __forceinline__ void ldsm_x4(uint32_t* r, uint32_t addr) {
    asm volatile(
        "ldmatrix.sync.aligned.m8n8.x4.shared.b16 {%0,%1,%2,%3}, [%4];"
        : "=r"(r[0]), "=r"(r[1]), "=r"(r[2]), "=r"(r[3]) : "r"(addr));
}

__device__ __forceinline__ uint32_t s2u(const void* p) {
    uint32_t a;
    asm("{ .reg .u64 t; cvta.to.shared.u64 t, %1; cvt.u32.u64 %0, t; }" : "=r"(a) : "l"(p));
    return a;
}

// ====== HMMA GEMM: C[M,N] = A[M,K] @ W[N,K]^T ======
// fp32 accuracy via fp16 hi/lo split of BOTH operands; 3 MMA passes (hh, lh, hl),
// dropped ll term error ~2^-22.
// Grid: (N/64, M/64, splits). Block 256 = 8 warps (4m x 2n), warp tile 16x32.
// BK = 32 (one barrier per 24 MMAs), double-buffered DYNAMIC smem (80 KB),
// register double-buffer with one-iteration LDG->consume distance.
// Fragment loads via ldmatrix.x4 (6 LDSM per K16 step instead of 24 LDS.32).
// AOP: 0 = A[m*lda+k]; 1 = gate y*silu(z); 2 = glu g1*silu(g2)
// EPI: 0 plain store (ldc), 2 softplus(+bias), 4 split-K partial -> g_part
#define SKB 40   // padded row stride (halves): conflict-free for LDSM (20r mod 32 distinct)
#define GSMEM (4 * 2 * 64 * SKB * 2)   // 81920 B

template <int AOP, int EPI>
__global__ void __launch_bounds__(256, 2)
mma_gemm(const float* __restrict__ A, int lda,
         const float* __restrict__ W, int ldb,
         const float* __restrict__ bias,
         float* __restrict__ C, int ldc, int kSpan)
{
    extern __shared__ __half smh[];
    // array ids: 0=Ah, 1=Al, 2=Bh, 3=Bl ; layout: ((arr*2+buf)*64 + row)*SKB + k
    auto sp = [&](int arr, int buf, int row, int k) -> __half* {
        return smh + ((size_t)((arr * 2 + buf) * 64 + row)) * SKB + k;
    };

    const int tid = threadIdx.x;
    const int wid = tid >> 5, lane = tid & 31;
    const int wm = wid >> 1, wn = wid & 1;       // 4 m-tiles x 2 n-tiles
    const int grp = lane >> 2, tq = lane & 3;

    const int m0 = blockIdx.y * 64;
    const int n0 = blockIdx.x * 64;
    const int kBase = blockIdx.z * kSpan;
    const int nChunks = kSpan >> 5;              // BK = 32

    float acc[4][4];
#pragma unroll
    for (int j = 0; j < 4; j++)
#pragma unroll
        for (int q = 0; q < 4; q++) acc[j][q] = 0.f;

    const int row = tid >> 2;     // 0..63
    const int kq = (tid & 3) * 8; // 0,8,16,24

    auto loadA = [&](int m, int k) -> float4 {
        if constexpr (AOP == 0) {
            return *(const float4*)(A + (size_t)m * lda + k);
        } else if constexpr (AOP == 1) {
            float4 y = *(const float4*)(g_y + (size_t)m * DINX + k);
            float4 z = *(const float4*)(g_xz + (size_t)m * 2048 + 1024 + k);
            return make_float4(y.x * siluf(z.x), y.y * siluf(z.y),
                               y.z * siluf(z.z), y.w * siluf(z.w));
        } else {
            float4 a = *(const float4*)(g_g + (size_t)m * 2048 + k);
            float4 b = *(const float4*)(g_g + (size_t)m * 2048 + 1024 + k);
            return make_float4(a.x * siluf(b.x), a.y * siluf(b.y),
                               a.z * siluf(b.z), a.w * siluf(b.w));
        }
    };

    float4 rgA[2], rgB[2];        // one chunk in flight
    auto fetch = [&](int c) {
        const int k = kBase + c * 32 + kq;
        rgA[0] = loadA(m0 + row, k);
        rgA[1] = loadA(m0 + row, k + 4);
        rgB[0] = *(const float4*)(W + (size_t)(n0 + row) * ldb + k);
        rgB[1] = *(const float4*)(W + (size_t)(n0 + row) * ldb + k + 4);
    };
    auto split8 = [&](const float4* v2, int arrH, int arrL, int buf) {
#pragma unroll
        for (int i = 0; i < 2; i++) {
            const float4 v = v2[i];
            const float vv[4] = {v.x, v.y, v.z, v.w};
            union { __half h[4]; uint2 u; } H, L;
#pragma unroll
            for (int q = 0; q < 4; q++) {
                __half h = __float2half_rn(vv[q]);
                H.h[q] = h;
                L.h[q] = __float2half_rn(vv[q] - __half2float(h));
            }
            *(uint2*)sp(arrH, buf, row, kq + i * 4) = H.u;
            *(uint2*)sp(arrL, buf, row, kq + i * 4) = L.u;
        }
    };
    auto store = [&](int buf) {
        split8(rgA, 0, 1, buf);
        split8(rgB, 2, 3, buf);
    };

    // ---- per-lane LDSM base addresses (buf 0; add BUFSTR*buf + 2*ko in loop) ----
    // A tiles: lt=0:(r,k0) lt=1:(r+8,k0) lt=2:(r,k8) lt=3:(r+8,k8)  -> a0..a3 order
    // B tiles: lt=0:(c,k0)=b0[nt=2p] lt=1:(c,k8)=b1[2p] lt=2:(c+8,k0)=b0[2p+1] lt=3:(c+8,k8)=b1[2p+1]
    const int lr8 = lane & 7, lt = lane >> 3;
    const int rowA = wm * 16 + (lt & 1) * 8 + lr8;
    const int kA = (lt >> 1) * 8;
    const int colB = wn * 32 + (lt >> 1) * 8 + lr8;
    const int kB = (lt & 1) * 8;
    const uint32_t smbase = s2u(smh);
    const uint32_t BUFSTR = 64 * SKB * 2;
    auto baseoff = [&](int arr, int r, int k) -> uint32_t {
        return smbase + (uint32_t)(((arr * 2) * 64 + r) * SKB + k) * 2;
    };
    const uint32_t aAh = baseoff(0, rowA, kA);
    const uint32_t aAl = baseoff(1, rowA, kA);
    const uint32_t aBh0 = baseoff(2, colB, kB);
    const uint32_t aBh1 = baseoff(2, colB + 16, kB);
    const uint32_t aBl0 = baseoff(3, colB, kB);
    const uint32_t aBl1 = baseoff(3, colB + 16, kB);

    fetch(0);
    store(0);
    if (nChunks > 1) fetch(1);
    __syncthreads();

    for (int c = 0; c < nChunks; c++) {
        const int buf = c & 1;
        const uint32_t bo = buf * BUFSTR;
        if (c + 1 < nChunks) {
            store(buf ^ 1);
            if (c + 2 < nChunks) fetch(c + 2);
        }
#pragma unroll
        for (int ks = 0; ks < 2; ks++) {
            const uint32_t ko2 = ks * 32;   // 16 halves = 32 bytes
            uint32_t Ah[4], Al[4], Bh[2][4], Bl[2][4];
            ldsm_x4(Ah, aAh + bo + ko2);
            ldsm_x4(Al, aAl + bo + ko2);
            ldsm_x4(Bh[0], aBh0 + bo + ko2);
            ldsm_x4(Bh[1], aBh1 + bo + ko2);
            ldsm_x4(Bl[0], aBl0 + bo + ko2);
            ldsm_x4(Bl[1], aBl1 + bo + ko2);
#pragma unroll
            for (int p = 0; p < 2; p++)
#pragma unroll
                for (int j = 0; j < 2; j++) {
                    const int nt = p * 2 + j;
                    mma16816(acc[nt], Ah, &Bh[p][2 * j]);
                    mma16816(acc[nt], Al, &Bh[p][2 * j]);
                    mma16816(acc[nt], Ah, &Bl[p][2 * j]);
                }
        }
        __syncthreads();
    }

    const int Nt = gridDim.x * 64;
    const int Mt = gridDim.y * 64;
#pragma unroll
    for (int nt = 0; nt < 4; nt++) {
        const int col = n0 + wn * 32 + nt * 8 + 2 * tq;
#pragma unroll
        for (int half = 0; half < 2; half++) {
            const int r = m0 + wm * 16 + grp + half * 8;
            float v0 = acc[nt][half * 2 + 0];
            float v1 = acc[nt][half * 2 + 1];
            if constexpr (EPI == 2) {
                v0 = softplusf(v0 + bias[col]);
                v1 = softplusf(v1 + bias[col + 1]);
            }
            float2 v = make_float2(v0, v1);
            if constexpr (EPI == 4) {
                *(float2*)(g_part + (size_t)blockIdx.z * Mt * Nt + (size_t)r * Nt + col) = v;
            } else {
                *(float2*)(C + (size_t)r * ldc + col) = v;
            }
        }
    }
}

__global__ void reduce_part(float* __restrict__ C, int MN, int ns)
{
    int i = blockIdx.x * 256 + threadIdx.x;
    if (i < MN) {
        float s = 0.f;
        for (int z = 0; z < ns; z++) s += g_part[(size_t)z * MN + i];
        C[i] = s;
    }
}

__global__ void reduce_bias(float* __restrict__ C, int MN, int ns,
                            const float* __restrict__ bias, int nmask)
{
    int i = blockIdx.x * 256 + threadIdx.x;
    if (i < MN) {
        float s = bias[i & nmask];
        for (int z = 0; z < ns; z++) s += g_part[(size_t)z * MN + i];
        C[i] = s;
    }
}

// ---------------- tokenize ----------------
__global__ void patch_mean_kernel(const float* __restrict__ images)
{
    const int blc = blockIdx.x;
    const int tid = threadIdx.x;
    const int y = tid >> 4, x = tid & 15;
    const int c = blc % 3, bl = blc / 3;
    const float* base = images + (size_t)blc * 224 * 224;
    float s = 0.f;
#pragma unroll 2
    for (int py = 0; py < 14; py++) {
        const float* row = base + (py * 16 + y) * 224 + x;
#pragma unroll
        for (int px = 0; px < 14; px++) s += row[px * 16];
    }
    g_meanp[(size_t)bl * 768 + c * 256 + tid] = s * (1.0f / 196.0f);
}

__global__ void token_kernel(const float* __restrict__ states,
                             const float* __restrict__ state_w, const float* __restrict__ state_b,
                             const float* __restrict__ actions,
                             const float* __restrict__ act_w, const float* __restrict__ act_b)
{
    const int bl = blockIdx.x;
    const int d = threadIdx.x;
    const int b = bl >> 6, li = bl & 63;
    const int base = b * SLEN + li * 4;

    g_hidden[(size_t)(base + 0) * DMODEL + d] = g_imgtok[(size_t)bl * DMODEL + d];

    const float* st = states + (size_t)bl * 3 * 7;
    float s = state_b[d];
#pragma unroll
    for (int j = 0; j < 7; j++) s = fmaf(st[j], state_w[d * 7 + j], s);
    g_hidden[(size_t)(base + 1) * DMODEL + d] = s;

#pragma unroll
    for (int t = 0; t < 2; t++) {
        const float* ac = actions + (size_t)(bl * 3 + t) * 4;
        float a = act_b[d];
#pragma unroll
        for (int j = 0; j < 4; j++) a = fmaf(ac[j], act_w[d * 4 + j], a);
        g_hidden[(size_t)(base + 2 + t) * DMODEL + d] = a;
    }
}

__global__ void aneg_kernel(const float* __restrict__ A_log)
{
    int i = blockIdx.x * 256 + threadIdx.x;
    if (i < LNUM * DINX * DSX) g_Aneg[i] = -expf(A_log[i]);
}

// residual += hidden (g_hidden if NS==0 which is also layer-0 zero-resid; else NS partials)
template <int NS>
__global__ void add_rms_kernel(const float* __restrict__ w)
{
    const int t = blockIdx.x;
    const int tid = threadIdx.x;      // 256
    const size_t base = (size_t)t * DMODEL;
    float a0, a1;
    if (NS == 0) {
        a0 = g_hidden[base + tid];
        a1 = g_hidden[base + 256 + tid];
    } else {
        a0 = 0.f; a1 = 0.f;
#pragma unroll
        for (int z = 0; z < NS; z++) {
            a0 += g_part[(size_t)z * TTOT * DMODEL + base + tid];
            a1 += g_part[(size_t)z * TTOT * DMODEL + base + 256 + tid];
        }
        a0 += g_resid[base + tid];
        a1 += g_resid[base + 256 + tid];
    }
    g_resid[base + tid] = a0;
    g_resid[base + 256 + tid] = a1;
    float ss = a0 * a0 + a1 * a1;
#pragma unroll
    for (int off = 16; off; off >>= 1) ss += __shfl_xor_sync(0xffffffffu, ss, off);
    __shared__ float red[8];
    if ((tid & 31) == 0) red[tid >> 5] = ss;
    __syncthreads();
    float tot = red[0] + red[1] + red[2] + red[3] + red[4] + red[5] + red[6] + red[7];
    float sc = rsqrtf(tot * (1.0f / 512.0f) + 1e-5f);
    g_xnorm[base + tid] = a0 * sc * w[tid];
    g_xnorm[base + 256 + tid] = a1 * sc * w[256 + tid];
}

__global__ void conv_kernel(const float* __restrict__ cw, const float* __restrict__ cb)
{
    int idx = blockIdx.x * 256 + threadIdx.x;
    if (idx >= TTOT * DINX) return;
    const int d = idx & (DINX - 1);
    const int t = idx >> 10;
    const int b = t >> 8, s = t & 255;
    const float* w4 = cw + d * 4;
    float acc = cb[d];
#pragma unroll
    for (int k = 0; k < 4; k++) {
        int ss = s - 3 + k;
        if (ss >= 0) acc = fmaf(w4[k], g_xz[(size_t)(b * SLEN + ss) * 2048 + d], acc);
    }
    g_xc[idx] = siluf(acc);
}

// ---------------- selective scan (smem-tiled, double-buffered) ----------------
// Grid (64, 2), block 256 = 16 d-channels x 16 states.
__global__ void scan_kernel(int l, const float* __restrict__ Dp_l)
{
    const int b = blockIdx.y;
    const int d0 = blockIdx.x << 4;
    const int tid = threadIdx.x;
    const int d = tid >> 4, n = tid & 15;
    const float Aa = g_Aneg[((size_t)l * DINX + d0 + d) * DSX + n];
    const float Dv = Dp_l[d0 + d];

    __shared__ float sdt[2][32][16], sxc[2][32][16], sBt[2][32][16], sCt[2][32][16];

    float r0[4], r1[4];
    const int ls = tid >> 4, ld = tid & 15;
    auto fetchT = [&](int tile) {
        const int t0 = (b << 8) + (tile << 5);
        r0[0] = g_dt[(size_t)(t0 + ls) * DINX + d0 + ld];
        r0[1] = g_xc[(size_t)(t0 + ls) * DINX + d0 + ld];
        r0[2] = g_proj[(t0 + ls) * 64 + 32 + ld];
        r0[3] = g_proj[(t0 + ls) * 64 + 48 + ld];
        r1[0] = g_dt[(size_t)(t0 + 16 + ls) * DINX + d0 + ld];
        r1[1] = g_xc[(size_t)(t0 + 16 + ls) * DINX + d0 + ld];
        r1[2] = g_proj[(t0 + 16 + ls) * 64 + 32 + ld];
        r1[3] = g_proj[(t0 + 16 + ls) * 64 + 48 + ld];
    };
    auto commitT = [&](int buf) {
        sdt[buf][ls][ld] = r0[0]; sxc[buf][ls][ld] = r0[1];
        sBt[buf][ls][ld] = r0[2]; sCt[buf][ls][ld] = r0[3];
        sdt[buf][ls + 16][ld] = r1[0]; sxc[buf][ls + 16][ld] = r1[1];
        sBt[buf][ls + 16][ld] = r1[2]; sCt[buf][ls + 16][ld] = r1[3];
    };

    fetchT(0); commitT(0);
    fetchT(1);
    __syncthreads();

    float h = 0.f;
    for (int tile = 0; tile < 8; tile++) {
        const int buf = tile & 1;
        const int t0 = (b << 8) + (tile << 5);
#pragma unroll 8
        for (int s = 0; s < 32; s++) {
            float dtv = sdt[buf][s][d];
            float xv  = sxc[buf][s][d];
            float Bn  = sBt[buf][s][n];
            float Cn  = sCt[buf][s][n];
            float a = __expf(dtv * Aa);
            h = fmaf(a, h, dtv * Bn * xv);
            float c = h * Cn;
            c += __shfl_down_sync(0xffffffffu, c, 8, 16);
            c += __shfl_down_sync(0xffffffffu, c, 4, 16);
            c += __shfl_down_sync(0xffffffffu, c, 2, 16);
            c += __shfl_down_sync(0xffffffffu, c, 1, 16);
            if (n == 0) g_y[(size_t)(t0 + s) * DINX + d0 + d] = fmaf(Dv, xv, c);
        }
        __syncthreads();
        if (tile + 1 < 8) {
            commitT((tile + 1) & 1);
            if (tile + 2 < 8) fetchT(tile + 2);
            __syncthreads();
        }
    }
}

// ---------------- head + loss ----------------
__global__ void head_kernel(const float* __restrict__ head_w, const float* __restrict__ head_b,
                            const float* __restrict__ labels,
                            float* __restrict__ out, int ofs, int write_preds)
{
    const int bl = blockIdx.x;
    const int w = threadIdx.x >> 5;
    const int lane = threadIdx.x & 31;
    const int t = w >> 2, a = w & 3;
    const int b = bl >> 6, li = bl & 63;
    const int tok = b * SLEN + li * 4 + 1 + t;
    const float* x = g_xnorm + (size_t)tok * DMODEL;
    const float* hw = head_w + a * DMODEL;
    float s = 0.f;
    for (int i = lane; i < DMODEL; i += 32) s = fmaf(x[i], hw[i], s);
#pragma unroll
    for (int off = 16; off; off >>= 1) s += __shfl_xor_sync(0xffffffffu, s, off);
    __shared__ float sd[12];
    if (lane == 0) {
        float pred = s + head_b[a];
        int idx = bl * 12 + t * 4 + a;
        if (write_preds) out[ofs + idx] = pred;
        sd[w] = fabsf(pred - labels[idx]);
    }
    __syncthreads();
    if (threadIdx.x == 0) {
        float acc = 0.f;
#pragma unroll
        for (int i = 0; i < 12; i++) acc += sd[i];
        g_la[bl] = acc * (1.0f / 12.0f);
    }
}

__global__ void loss_kernel(const int* __restrict__ seqlen, float* __restrict__ out, int write_loss)
{
    const int tid = threadIdx.x;
    const int b = tid >> 6, li = tid & 63;
    float m = (li < seqlen[b]) ? 1.f : 0.f;
    __shared__ float sv[128], sm[128];
    sv[tid] = g_la[tid] * m;
    sm[tid] = m;
    __syncthreads();
    if (tid == 0 && write_loss) {
        float s0 = 0, c0 = 0, s1 = 0, c1 = 0;
        for (int i = 0; i < 64; i++) { s0 += sv[i]; c0 += sm[i]; s1 += sv[64 + i]; c1 += sm[64 + i]; }
        float l0 = s0 / fmaxf(c0, 1.f);
        float l1 = s1 / fmaxf(c1, 1.f);
        out[0] = 0.5f * (l0 + l1);
    }
}

// ---------------- host ----------------
extern "C" void kernel_launch(void* const* d_in, const int* in_sizes, int n_in,
                              void* d_out, int out_size)
{
    const float* images   = (const float*)d_in[0];
    const int*   seqlen   = (const int*)  d_in[1];
    const float* states   = (const float*)d_in[2];
    const float* actions  = (const float*)d_in[3];
    const float* labels   = (const float*)d_in[4];
    const float* patch_w  = (const float*)d_in[5];
    const float* patch_b  = (const float*)d_in[6];
    const float* state_w  = (const float*)d_in[7];
    const float* state_b  = (const float*)d_in[8];
    const float* act_w    = (const float*)d_in[9];
    const float* act_b    = (const float*)d_in[10];
    const float* norm1_w  = (const float*)d_in[11];
    const float* in_proj_w= (const float*)d_in[12];
    const float* conv_w   = (const float*)d_in[13];
    const float* conv_b   = (const float*)d_in[14];
    const float* x_proj_w = (const float*)d_in[15];
    const float* dt_w     = (const float*)d_in[16];
    const float* dt_b     = (const float*)d_in[17];
    const float* A_log    = (const float*)d_in[18];
    const float* Dp       = (const float*)d_in[19];
    const float* out_proj_w=(const float*)d_in[20];
    const float* norm2_w  = (const float*)d_in[21];
    const float* fc1_w    = (const float*)d_in[22];
    const float* fc2_w    = (const float*)d_in[23];
    const float* norm_f_w = (const float*)d_in[24];
    const float* head_w   = (const float*)d_in[25];
    const float* head_b   = (const float*)d_in[26];
    float* out = (float*)d_out;

    float *p_meanp, *p_imgtok, *p_xnorm, *p_xz, *p_xc, *p_proj, *p_dt, *p_g;
    cudaGetSymbolAddress((void**)&p_meanp, g_meanp);
    cudaGetSymbolAddress((void**)&p_imgtok, g_imgtok);
    cudaGetSymbolAddress((void**)&p_xnorm, g_xnorm);
    cudaGetSymbolAddress((void**)&p_xz, g_xz);
    cudaGetSymbolAddress((void**)&p_xc, g_xc);
    cudaGetSymbolAddress((void**)&p_proj, g_proj);
    cudaGetSymbolAddress((void**)&p_dt, g_dt);
    cudaGetSymbolAddress((void**)&p_g, g_g);

    // allow 80 KB dynamic smem on every GEMM instantiation (idempotent)
    cudaFuncSetAttribute(mma_gemm<0,0>, cudaFuncAttributeMaxDynamicSharedMemorySize, GSMEM);
    cudaFuncSetAttribute(mma_gemm<0,2>, cudaFuncAttributeMaxDynamicSharedMemorySize, GSMEM);
    cudaFuncSetAttribute(mma_gemm<0,4>, cudaFuncAttributeMaxDynamicSharedMemorySize, GSMEM);
    cudaFuncSetAttribute(mma_gemm<1,4>, cudaFuncAttributeMaxDynamicSharedMemorySize, GSMEM);
    cudaFuncSetAttribute(mma_gemm<2,4>, cudaFuncAttributeMaxDynamicSharedMemorySize, GSMEM);

    // prologue
    aneg_kernel<<<(LNUM * DINX * DSX + 255) / 256, 256>>>(A_log);
    patch_mean_kernel<<<384, 256>>>(images);
    // img tokens: [128,512] = meanp[128,768] @ patch_w^T + patch_b  (split-K 4)
    mma_gemm<0,4><<<dim3(8, 2, 4), 256, GSMEM>>>(p_meanp, 768, patch_w, 768,
                                                 nullptr, nullptr, 512, 192);
    reduce_bias<<<(128 * 512 + 255) / 256, 256>>>(p_imgtok, 128 * 512, 4, patch_b, 511);
    token_kernel<<<128, 512>>>(states, state_w, state_b, actions, act_w, act_b);

    for (int l = 0; l < LNUM; l++) {
        if (l == 0) add_rms_kernel<0><<<TTOT, 256>>>(norm1_w);
        else        add_rms_kernel<4><<<TTOT, 256>>>(norm1_w + l * DMODEL);
        // xz[512,2048] = xnorm @ in_proj^T (K=512)
        mma_gemm<0,0><<<dim3(32, 8, 1), 256, GSMEM>>>(p_xnorm, 512,
            in_proj_w + (size_t)l * 2048 * 512, 512, nullptr, p_xz, 2048, 512);
        conv_kernel<<<(TTOT * DINX + 255) / 256, 256>>>(conv_w + (size_t)l * DINX * 4,
                                                        conv_b + l * DINX);
        // proj[512,64] = xc @ x_proj^T (K=1024, split-K 8)
        mma_gemm<0,4><<<dim3(1, 8, 8), 256, GSMEM>>>(p_xc, 1024,
            x_proj_w + (size_t)l * 64 * 1024, 1024, nullptr, nullptr, 64, 128);
        reduce_part<<<(TTOT * 64 + 255) / 256, 256>>>(p_proj, TTOT * 64, 8);
        // dt[512,1024] = softplus(dtr @ dt_w^T + dt_b); dtr = proj[:, :32] (lda=64)
        mma_gemm<0,2><<<dim3(16, 8, 1), 256, GSMEM>>>(p_proj, 64,
            dt_w + (size_t)l * 1024 * 32, 32, dt_b + l * DINX, p_dt, 1024, 32);
        scan_kernel<<<dim3(64, 2), 256>>>(l, Dp + l * DINX);
        // hidden_partials = (y*silu(z)) @ out_proj^T (K=1024, split-K 4, gate fused in A)
        mma_gemm<1,4><<<dim3(8, 8, 4), 256, GSMEM>>>(nullptr, 0,
            out_proj_w + (size_t)l * 512 * 1024, 1024, nullptr, nullptr, 512, 256);
        add_rms_kernel<4><<<TTOT, 256>>>(norm2_w + l * DMODEL);
        // g[512,2048] = xnorm @ fc1^T (K=512)
        mma_gemm<0,0><<<dim3(32, 8, 1), 256, GSMEM>>>(p_xnorm, 512,
            fc1_w + (size_t)l * 2048 * 512, 512, nullptr, p_g, 2048, 512);
        // hidden_partials = (g1*silu(g2)) @ fc2^T (K=1024, split-K 4, GLU fused in A)
        mma_gemm<2,4><<<dim3(8, 8, 4), 256, GSMEM>>>(nullptr, 0,
            fc2_w + (size_t)l * 512 * 1024, 1024, nullptr, nullptr, 512, 256);
    }

    // final norm + head + loss
    add_rms_kernel<4><<<TTOT, 256>>>(norm_f_w);
    int write_preds = (out_size >= 1536) ? 1 : 0;
    int ofs = (out_size == 1536) ? 0 : 1;
    int write_loss = (out_size != 1536) ? 1 : 0;
    head_kernel<<<128, 384>>>(head_w, head_b, labels, out, ofs, write_preds);
    loss_kernel<<<1, 128>>>(seqlen, out, write_loss);
}

// round 13
// speedup vs baseline: 1.6200x; 1.0136x over previous
#include <cuda_runtime.h>
#include <cuda_fp16.h>
#include <math.h>
#include <stdint.h>

#define LNUM 8
#define DMODEL 512
#define DINX 1024
#define DSX 16
#define SLEN 256
#define TTOT 512   // BATCH * SLEN tokens

// ---------------- scratch (static device memory; no allocations) ----------------
__device__ float g_meanp[128 * 768];
__device__ float g_hidden[TTOT * DMODEL];
__device__ float g_resid[TTOT * DMODEL];
__device__ float g_xnorm[TTOT * DMODEL];
__device__ float g_xz[TTOT * 2 * DINX];
__device__ float g_dt[TTOT * DINX];
__device__ float g_y[TTOT * DINX];
__device__ float g_g[TTOT * 2 * DINX];
__device__ float g_Aneg[LNUM * DINX * DSX];
__device__ float g_part[4 * TTOT * DMODEL];   // split-K partial slab (4 MB)
__device__ float g_la[128];

__device__ __forceinline__ float siluf(float x) { return x / (1.0f + __expf(-x)); }
__device__ __forceinline__ float softplusf(float x) {
    return fmaxf(x, 0.0f) + log1pf(__expf(-fabsf(x)));
}

// ---- warp-level fp16 HMMA (sm_80+ PTX; tensor-core path that compiles for sm_103) ----
__device__ __forceinline__ void mma16816(float* c, const uint32_t* a, const uint32_t* b) {
    asm volatile(
        "mma.sync.aligned.m16n8k16.row.col.f32.f16.f16.f32 "
        "{%0,%1,%2,%3}, {%4,%5,%6,%7}, {%8,%9}, {%0,%1,%2,%3};"
        : "+f"(c[0]), "+f"(c[1]), "+f"(c[2]), "+f"(c[3])
        : "r"(a[0]), "r"(a[1]), "r"(a[2]), "r"(a[3]), "r"(b[0]), "r"(b[1]));
}

__device__ __forceinline__ void ldsm_x4(uint32_t* r, uint32_t addr) {
    asm volatile(
        "ldmatrix.sync.aligned.m8n8.x4.shared.b16 {%0,%1,%2,%3}, [%4];"
        : "=r"(r[0]), "=r"(r[1]), "=r"(r[2]), "=r"(r[3]) : "r"(addr));
}

__device__ __forceinline__ uint32_t s2u(const void* p) {
    uint32_t a;
    asm("{ .reg .u64 t; cvta.to.shared.u64 t, %1; cvt.u32.u64 %0, t; }" : "=r"(a) : "l"(p));
    return a;
}

// ====== HMMA GEMM: C[M,N] = A[M,K] @ W[N,K]^T ======
// fp32 accuracy via fp16 hi/lo split of BOTH operands; 3 MMA passes (hh, lh, hl).
// BK=32, double-buffered dynamic smem, register prefetch, LDSM fragment loads.
// AOP: 0 = A[m*lda+k]; 1 = gate y*silu(z); 2 = glu g1*silu(g2);
//      3 = sum of 8 split-K partials (g_part, [z][512][64]);
//      4 = fused causal-conv+silu of g_xz (A param = conv_w, bias param = conv_b)
// EPI: 0 plain store (ldc), 2 softplus(+bias), 4 split-K partial -> g_part
#define SKB 40
#define GSMEM (4 * 2 * 64 * SKB * 2)   // 81920 B

template <int AOP, int EPI>
__global__ void __launch_bounds__(256, 2)
mma_gemm(const float* __restrict__ A, int lda,
         const float* __restrict__ W, int ldb,
         const float* __restrict__ bias,
         float* __restrict__ C, int ldc, int kSpan)
{
    extern __shared__ __half smh[];
    auto sp = [&](int arr, int buf, int row, int k) -> __half* {
        return smh + ((size_t)((arr * 2 + buf) * 64 + row)) * SKB + k;
    };

    const int tid = threadIdx.x;
    const int wid = tid >> 5, lane = tid & 31;
    const int wm = wid >> 1, wn = wid & 1;
    const int grp = lane >> 2, tq = lane & 3;

    const int m0 = blockIdx.y * 64;
    const int n0 = blockIdx.x * 64;
    const int kBase = blockIdx.z * kSpan;
    const int nChunks = kSpan >> 5;

    float acc[4][4];
#pragma unroll
    for (int j = 0; j < 4; j++)
#pragma unroll
        for (int q = 0; q < 4; q++) acc[j][q] = 0.f;

    const int row = tid >> 2;
    const int kq = (tid & 3) * 8;

    auto loadA = [&](int m, int k) -> float4 {
        if constexpr (AOP == 0) {
            return *(const float4*)(A + (size_t)m * lda + k);
        } else if constexpr (AOP == 1) {
            float4 y = *(const float4*)(g_y + (size_t)m * DINX + k);
            float4 z = *(const float4*)(g_xz + (size_t)m * 2048 + 1024 + k);
            return make_float4(y.x * siluf(z.x), y.y * siluf(z.y),
                               y.z * siluf(z.z), y.w * siluf(z.w));
        } else if constexpr (AOP == 2) {
            float4 a = *(const float4*)(g_g + (size_t)m * 2048 + k);
            float4 b = *(const float4*)(g_g + (size_t)m * 2048 + 1024 + k);
            return make_float4(a.x * siluf(b.x), a.y * siluf(b.y),
                               a.z * siluf(b.z), a.w * siluf(b.w));
        } else if constexpr (AOP == 3) {
            float4 s = make_float4(0.f, 0.f, 0.f, 0.f);
#pragma unroll
            for (int z = 0; z < 8; z++) {
                float4 p = *(const float4*)(g_part + (size_t)z * 32768 + m * 64 + k);
                s.x += p.x; s.y += p.y; s.z += p.z; s.w += p.w;
            }
            return s;
        } else {
            // AOP==4: xc[m, k..k+3] = silu(conv(xz)); A = conv_w, bias = conv_b
            const int sstep = m & 255;
            const float4 cw0 = *(const float4*)(A + (k + 0) * 4);
            const float4 cw1 = *(const float4*)(A + (k + 1) * 4);
            const float4 cw2 = *(const float4*)(A + (k + 2) * 4);
            const float4 cw3 = *(const float4*)(A + (k + 3) * 4);
            float4 r = *(const float4*)(bias + k);
#pragma unroll
            for (int j = 0; j < 4; j++) {
                if (sstep - 3 + j >= 0) {
                    float4 xz4 = *(const float4*)(g_xz + (size_t)(m - 3 + j) * 2048 + k);
                    const float w0 = j == 0 ? cw0.x : j == 1 ? cw0.y : j == 2 ? cw0.z : cw0.w;
                    const float w1 = j == 0 ? cw1.x : j == 1 ? cw1.y : j == 2 ? cw1.z : cw1.w;
                    const float w2 = j == 0 ? cw2.x : j == 1 ? cw2.y : j == 2 ? cw2.z : cw2.w;
                    const float w3 = j == 0 ? cw3.x : j == 1 ? cw3.y : j == 2 ? cw3.z : cw3.w;
                    r.x = fmaf(w0, xz4.x, r.x);
                    r.y = fmaf(w1, xz4.y, r.y);
                    r.z = fmaf(w2, xz4.z, r.z);
                    r.w = fmaf(w3, xz4.w, r.w);
                }
            }
            return make_float4(siluf(r.x), siluf(r.y), siluf(r.z), siluf(r.w));
        }
    };

    float4 rgA[2], rgB[2];
    auto fetch = [&](int c) {
        const int k = kBase + c * 32 + kq;
        rgA[0] = loadA(m0 + row, k);
        rgA[1] = loadA(m0 + row, k + 4);
        rgB[0] = *(const float4*)(W + (size_t)(n0 + row) * ldb + k);
        rgB[1] = *(const float4*)(W + (size_t)(n0 + row) * ldb + k + 4);
    };
    auto split8 = [&](const float4* v2, int arrH, int arrL, int buf) {
#pragma unroll
        for (int i = 0; i < 2; i++) {
            const float4 v = v2[i];
            const float vv[4] = {v.x, v.y, v.z, v.w};
            union { __half h[4]; uint2 u; } H, L;
#pragma unroll
            for (int q = 0; q < 4; q++) {
                __half h = __float2half_rn(vv[q]);
                H.h[q] = h;
                L.h[q] = __float2half_rn(vv[q] - __half2float(h));
            }
            *(uint2*)sp(arrH, buf, row, kq + i * 4) = H.u;
            *(uint2*)sp(arrL, buf, row, kq + i * 4) = L.u;
        }
    };
    auto store = [&](int buf) {
        split8(rgA, 0, 1, buf);
        split8(rgB, 2, 3, buf);
    };

    const int lr8 = lane & 7, lt = lane >> 3;
    const int rowA = wm * 16 + (lt & 1) * 8 + lr8;
    const int kA = (lt >> 1) * 8;
    const int colB = wn * 32 + (lt >> 1) * 8 + lr8;
    const int kB = (lt & 1) * 8;
    const uint32_t smbase = s2u(smh);
    const uint32_t BUFSTR = 64 * SKB * 2;
    auto baseoff = [&](int arr, int r, int k) -> uint32_t {
        return smbase + (uint32_t)(((arr * 2) * 64 + r) * SKB + k) * 2;
    };
    const uint32_t aAh = baseoff(0, rowA, kA);
    const uint32_t aAl = baseoff(1, rowA, kA);
    const uint32_t aBh0 = baseoff(2, colB, kB);
    const uint32_t aBh1 = baseoff(2, colB + 16, kB);
    const uint32_t aBl0 = baseoff(3, colB, kB);
    const uint32_t aBl1 = baseoff(3, colB + 16, kB);

    fetch(0);
    store(0);
    if (nChunks > 1) fetch(1);
    __syncthreads();

    for (int c = 0; c < nChunks; c++) {
        const int buf = c & 1;
        const uint32_t bo = buf * BUFSTR;
        if (c + 1 < nChunks) {
            store(buf ^ 1);
            if (c + 2 < nChunks) fetch(c + 2);
        }
#pragma unroll
        for (int ks = 0; ks < 2; ks++) {
            const uint32_t ko2 = ks * 32;
            uint32_t Ah[4], Al[4], Bh[2][4], Bl[2][4];
            ldsm_x4(Ah, aAh + bo + ko2);
            ldsm_x4(Al, aAl + bo + ko2);
            ldsm_x4(Bh[0], aBh0 + bo + ko2);
            ldsm_x4(Bh[1], aBh1 + bo + ko2);
            ldsm_x4(Bl[0], aBl0 + bo + ko2);
            ldsm_x4(Bl[1], aBl1 + bo + ko2);
#pragma unroll
            for (int p = 0; p < 2; p++)
#pragma unroll
                for (int j = 0; j < 2; j++) {
                    const int nt = p * 2 + j;
                    mma16816(acc[nt], Ah, &Bh[p][2 * j]);
                    mma16816(acc[nt], Al, &Bh[p][2 * j]);
                    mma16816(acc[nt], Ah, &Bl[p][2 * j]);
                }
        }
        __syncthreads();
    }

    const int Nt = gridDim.x * 64;
    const int Mt = gridDim.y * 64;
#pragma unroll
    for (int nt = 0; nt < 4; nt++) {
        const int col = n0 + wn * 32 + nt * 8 + 2 * tq;
#pragma unroll
        for (int half = 0; half < 2; half++) {
            const int r = m0 + wm * 16 + grp + half * 8;
            float v0 = acc[nt][half * 2 + 0];
            float v1 = acc[nt][half * 2 + 1];
            if constexpr (EPI == 2) {
                v0 = softplusf(v0 + bias[col]);
                v1 = softplusf(v1 + bias[col + 1]);
            }
            float2 v = make_float2(v0, v1);
            if constexpr (EPI == 4) {
                *(float2*)(g_part + (size_t)blockIdx.z * Mt * Nt + (size_t)r * Nt + col) = v;
            } else {
                *(float2*)(C + (size_t)r * ldc + col) = v;
            }
        }
    }
}

// ---------------- tokenize ----------------
__global__ void patch_mean_kernel(const float* __restrict__ images)
{
    const int blc = blockIdx.x;
    const int tid = threadIdx.x;
    const int y = tid >> 4, x = tid & 15;
    const int c = blc % 3, bl = blc / 3;
    const float* base = images + (size_t)blc * 224 * 224;
    float s = 0.f;
#pragma unroll 2
    for (int py = 0; py < 14; py++) {
        const float* row = base + (py * 16 + y) * 224 + x;
#pragma unroll
        for (int px = 0; px < 14; px++) s += row[px * 16];
    }
    g_meanp[(size_t)bl * 768 + c * 256 + tid] = s * (1.0f / 196.0f);
}

// img token = patch_b + sum of 4 patch-GEMM partials (reduce_bias fused here)
__global__ void token_kernel(const float* __restrict__ patch_b,
                             const float* __restrict__ states,
                             const float* __restrict__ state_w, const float* __restrict__ state_b,
                             const float* __restrict__ actions,
                             const float* __restrict__ act_w, const float* __restrict__ act_b)
{
    const int bl = blockIdx.x;
    const int d = threadIdx.x;
    const int b = bl >> 6, li = bl & 63;
    const int base = b * SLEN + li * 4;

    float iv = patch_b[d];
#pragma unroll
    for (int z = 0; z < 4; z++) iv += g_part[(size_t)z * 65536 + bl * 512 + d];
    g_hidden[(size_t)(base + 0) * DMODEL + d] = iv;

    const float* st = states + (size_t)bl * 3 * 7;
    float s = state_b[d];
#pragma unroll
    for (int j = 0; j < 7; j++) s = fmaf(st[j], state_w[d * 7 + j], s);
    g_hidden[(size_t)(base + 1) * DMODEL + d] = s;

#pragma unroll
    for (int t = 0; t < 2; t++) {
        const float* ac = actions + (size_t)(bl * 3 + t) * 4;
        float a = act_b[d];
#pragma unroll
        for (int j = 0; j < 4; j++) a = fmaf(ac[j], act_w[d * 4 + j], a);
        g_hidden[(size_t)(base + 2 + t) * DMODEL + d] = a;
    }
}

__global__ void aneg_kernel(const float* __restrict__ A_log)
{
    int i = blockIdx.x * 256 + threadIdx.x;
    if (i < LNUM * DINX * DSX) g_Aneg[i] = -expf(A_log[i]);
}

template <int NS>
__global__ void add_rms_kernel(const float* __restrict__ w)
{
    const int t = blockIdx.x;
    const int tid = threadIdx.x;
    const size_t base = (size_t)t * DMODEL;
    float a0, a1;
    if (NS == 0) {
        a0 = g_hidden[base + tid];
        a1 = g_hidden[base + 256 + tid];
    } else {
        a0 = 0.f; a1 = 0.f;
#pragma unroll
        for (int z = 0; z < NS; z++) {
            a0 += g_part[(size_t)z * TTOT * DMODEL + base + tid];
            a1 += g_part[(size_t)z * TTOT * DMODEL + base + 256 + tid];
        }
        a0 += g_resid[base + tid];
        a1 += g_resid[base + 256 + tid];
    }
    g_resid[base + tid] = a0;
    g_resid[base + 256 + tid] = a1;
    float ss = a0 * a0 + a1 * a1;
#pragma unroll
    for (int off = 16; off; off >>= 1) ss += __shfl_xor_sync(0xffffffffu, ss, off);
    __shared__ float red[8];
    if ((tid & 31) == 0) red[tid >> 5] = ss;
    __syncthreads();
    float tot = red[0] + red[1] + red[2] + red[3] + red[4] + red[5] + red[6] + red[7];
    float sc = rsqrtf(tot * (1.0f / 512.0f) + 1e-5f);
    g_xnorm[base + tid] = a0 * sc * w[tid];
    g_xnorm[base + 256 + tid] = a1 * sc * w[256 + tid];
}

// ---------------- selective scan (conv + partial-reduce fused into staging) ----------------
// Grid (64, 2), block 256 = 16 d-channels x 16 states.
__global__ void scan_kernel(int l, const float* __restrict__ Dp_l,
                            const float* __restrict__ cw, const float* __restrict__ cb)
{
    const int b = blockIdx.y;
    const int d0 = blockIdx.x << 4;
    const int tid = threadIdx.x;
    const int d = tid >> 4, n = tid & 15;
    const float Aa = g_Aneg[((size_t)l * DINX + d0 + d) * DSX + n];
    const float Dv = Dp_l[d0 + d];

    __shared__ float sdt[2][32][16], sxc[2][32][16], sBt[2][32][16], sCt[2][32][16];

    const int ls = tid >> 4, ld = tid & 15;   // staging: step ls/(ls+16), channel ld
    // hoisted conv weights for this thread's channel
    const float4 cwv = *(const float4*)(cw + (d0 + ld) * 4);
    const float cbv = cb[d0 + ld];

    float r0[4], r1[4];
    auto convAt = [&](int sstep) -> float {   // sstep = step within batch (0..255)
        const int t = (b << 8) + sstep;
        float a = cbv;
        if (sstep >= 3) {
            a = fmaf(cwv.x, g_xz[(size_t)(t - 3) * 2048 + d0 + ld], a);
            a = fmaf(cwv.y, g_xz[(size_t)(t - 2) * 2048 + d0 + ld], a);
            a = fmaf(cwv.z, g_xz[(size_t)(t - 1) * 2048 + d0 + ld], a);
        } else {
            if (sstep >= 3 - 0) {}
            if (sstep - 3 + 0 >= 0) a = fmaf(cwv.x, g_xz[(size_t)(t - 3) * 2048 + d0 + ld], a);
            if (sstep - 3 + 1 >= 0) a = fmaf(cwv.y, g_xz[(size_t)(t - 2) * 2048 + d0 + ld], a);
            if (sstep - 3 + 2 >= 0) a = fmaf(cwv.z, g_xz[(size_t)(t - 1) * 2048 + d0 + ld], a);
        }
        a = fmaf(cwv.w, g_xz[(size_t)t * 2048 + d0 + ld], a);
        return siluf(a);
    };
    auto sumPart = [&](int t, int col) -> float {
        float s = 0.f;
#pragma unroll
        for (int z = 0; z < 8; z++) s += g_part[(size_t)z * 32768 + t * 64 + col];
        return s;
    };
    auto fetchT = [&](int tile) {
        const int s0 = (tile << 5) + ls;
        const int t0 = (b << 8) + s0;
        r0[0] = g_dt[(size_t)t0 * DINX + d0 + ld];
        r0[1] = convAt(s0);
        r0[2] = sumPart(t0, 32 + ld);
        r0[3] = sumPart(t0, 48 + ld);
        r1[0] = g_dt[(size_t)(t0 + 16) * DINX + d0 + ld];
        r1[1] = convAt(s0 + 16);
        r1[2] = sumPart(t0 + 16, 32 + ld);
        r1[3] = sumPart(t0 + 16, 48 + ld);
    };
    auto commitT = [&](int buf) {
        sdt[buf][ls][ld] = r0[0]; sxc[buf][ls][ld] = r0[1];
        sBt[buf][ls][ld] = r0[2]; sCt[buf][ls][ld] = r0[3];
        sdt[buf][ls + 16][ld] = r1[0]; sxc[buf][ls + 16][ld] = r1[1];
        sBt[buf][ls + 16][ld] = r1[2]; sCt[buf][ls + 16][ld] = r1[3];
    };

    fetchT(0); commitT(0);
    fetchT(1);
    __syncthreads();

    float h = 0.f;
    for (int tile = 0; tile < 8; tile++) {
        const int buf = tile & 1;
        const int t0 = (b << 8) + (tile << 5);
#pragma unroll 8
        for (int s = 0; s < 32; s++) {
            float dtv = sdt[buf][s][d];
            float xv  = sxc[buf][s][d];
            float Bn  = sBt[buf][s][n];
            float Cn  = sCt[buf][s][n];
            float a = __expf(dtv * Aa);
            h = fmaf(a, h, dtv * Bn * xv);
            float c = h * Cn;
            c += __shfl_down_sync(0xffffffffu, c, 8, 16);
            c += __shfl_down_sync(0xffffffffu, c, 4, 16);
            c += __shfl_down_sync(0xffffffffu, c, 2, 16);
            c += __shfl_down_sync(0xffffffffu, c, 1, 16);
            if (n == 0) g_y[(size_t)(t0 + s) * DINX + d0 + d] = fmaf(Dv, xv, c);
        }
        __syncthreads();
        if (tile + 1 < 8) {
            commitT((tile + 1) & 1);
            if (tile + 2 < 8) fetchT(tile + 2);
            __syncthreads();
        }
    }
}

// ---------------- head + loss ----------------
__global__ void head_kernel(const float* __restrict__ head_w, const float* __restrict__ head_b,
                            const float* __restrict__ labels,
                            float* __restrict__ out, int ofs, int write_preds)
{
    const int bl = blockIdx.x;
    const int w = threadIdx.x >> 5;
    const int lane = threadIdx.x & 31;
    const int t = w >> 2, a = w & 3;
    const int b = bl >> 6, li = bl & 63;
    const int tok = b * SLEN + li * 4 + 1 + t;
    const float* x = g_xnorm + (size_t)tok * DMODEL;
    const float* hw = head_w + a * DMODEL;
    float s = 0.f;
    for (int i = lane; i < DMODEL; i += 32) s = fmaf(x[i], hw[i], s);
#pragma unroll
    for (int off = 16; off; off >>= 1) s += __shfl_xor_sync(0xffffffffu, s, off);
    __shared__ float sd[12];
    if (lane == 0) {
        float pred = s + head_b[a];
        int idx = bl * 12 + t * 4 + a;
        if (write_preds) out[ofs + idx] = pred;
        sd[w] = fabsf(pred - labels[idx]);
    }
    __syncthreads();
    if (threadIdx.x == 0) {
        float acc = 0.f;
#pragma unroll
        for (int i = 0; i < 12; i++) acc += sd[i];
        g_la[bl] = acc * (1.0f / 12.0f);
    }
}

__global__ void loss_kernel(const int* __restrict__ seqlen, float* __restrict__ out, int write_loss)
{
    const int tid = threadIdx.x;
    const int b = tid >> 6, li = tid & 63;
    float m = (li < seqlen[b]) ? 1.f : 0.f;
    __shared__ float sv[128], sm[128];
    sv[tid] = g_la[tid] * m;
    sm[tid] = m;
    __syncthreads();
    if (tid == 0 && write_loss) {
        float s0 = 0, c0 = 0, s1 = 0, c1 = 0;
        for (int i = 0; i < 64; i++) { s0 += sv[i]; c0 += sm[i]; s1 += sv[64 + i]; c1 += sm[64 + i]; }
        float l0 = s0 / fmaxf(c0, 1.f);
        float l1 = s1 / fmaxf(c1, 1.f);
        out[0] = 0.5f * (l0 + l1);
    }
}

// ---------------- host ----------------
extern "C" void kernel_launch(void* const* d_in, const int* in_sizes, int n_in,
                              void* d_out, int out_size)
{
    const float* images   = (const float*)d_in[0];
    const int*   seqlen   = (const int*)  d_in[1];
    const float* states   = (const float*)d_in[2];
    const float* actions  = (const float*)d_in[3];
    const float* labels   = (const float*)d_in[4];
    const float* patch_w  = (const float*)d_in[5];
    const float* patch_b  = (const float*)d_in[6];
    const float* state_w  = (const float*)d_in[7];
    const float* state_b  = (const float*)d_in[8];
    const float* act_w    = (const float*)d_in[9];
    const float* act_b    = (const float*)d_in[10];
    const float* norm1_w  = (const float*)d_in[11];
    const float* in_proj_w= (const float*)d_in[12];
    const float* conv_w   = (const float*)d_in[13];
    const float* conv_b   = (const float*)d_in[14];
    const float* x_proj_w = (const float*)d_in[15];
    const float* dt_w     = (const float*)d_in[16];
    const float* dt_b     = (const float*)d_in[17];
    const float* A_log    = (const float*)d_in[18];
    const float* Dp       = (const float*)d_in[19];
    const float* out_proj_w=(const float*)d_in[20];
    const float* norm2_w  = (const float*)d_in[21];
    const float* fc1_w    = (const float*)d_in[22];
    const float* fc2_w    = (const float*)d_in[23];
    const float* norm_f_w = (const float*)d_in[24];
    const float* head_w   = (const float*)d_in[25];
    const float* head_b   = (const float*)d_in[26];
    float* out = (float*)d_out;

    float *p_meanp, *p_xnorm, *p_xz, *p_dt, *p_g;
    cudaGetSymbolAddress((void**)&p_meanp, g_meanp);
    cudaGetSymbolAddress((void**)&p_xnorm, g_xnorm);
    cudaGetSymbolAddress((void**)&p_xz, g_xz);
    cudaGetSymbolAddress((void**)&p_dt, g_dt);
    cudaGetSymbolAddress((void**)&p_g, g_g);

    cudaFuncSetAttribute(mma_gemm<0,0>, cudaFuncAttributeMaxDynamicSharedMemorySize, GSMEM);
    cudaFuncSetAttribute(mma_gemm<0,4>, cudaFuncAttributeMaxDynamicSharedMemorySize, GSMEM);
    cudaFuncSetAttribute(mma_gemm<1,4>, cudaFuncAttributeMaxDynamicSharedMemorySize, GSMEM);
    cudaFuncSetAttribute(mma_gemm<2,4>, cudaFuncAttributeMaxDynamicSharedMemorySize, GSMEM);
    cudaFuncSetAttribute(mma_gemm<3,2>, cudaFuncAttributeMaxDynamicSharedMemorySize, GSMEM);
    cudaFuncSetAttribute(mma_gemm<4,4>, cudaFuncAttributeMaxDynamicSharedMemorySize, GSMEM);

    // prologue
    aneg_kernel<<<(LNUM * DINX * DSX + 255) / 256, 256>>>(A_log);
    patch_mean_kernel<<<384, 256>>>(images);
    // img token partials: [128,512] = meanp[128,768] @ patch_w^T  (split-K 4)
    mma_gemm<0,4><<<dim3(8, 2, 4), 256, GSMEM>>>(p_meanp, 768, patch_w, 768,
                                                 nullptr, nullptr, 512, 192);
    token_kernel<<<128, 512>>>(patch_b, states, state_w, state_b, actions, act_w, act_b);

    for (int l = 0; l < LNUM; l++) {
        if (l == 0) add_rms_kernel<0><<<TTOT, 256>>>(norm1_w);
        else        add_rms_kernel<4><<<TTOT, 256>>>(norm1_w + l * DMODEL);
        // xz[512,2048] = xnorm @ in_proj^T (K=512)
        mma_gemm<0,0><<<dim3(32, 8, 1), 256, GSMEM>>>(p_xnorm, 512,
            in_proj_w + (size_t)l * 2048 * 512, 512, nullptr, p_xz, 2048, 512);
        // proj partials[8][512,64] = conv(xz) @ x_proj^T (conv fused in A-load; split-K 8)
        mma_gemm<4,4><<<dim3(1, 8, 8), 256, GSMEM>>>(conv_w + (size_t)l * DINX * 4, 0,
            x_proj_w + (size_t)l * 64 * 1024, 1024, conv_b + l * DINX, nullptr, 64, 128);
        // dt[512,1024] = softplus(sum(partials)[:, :32] @ dt_w^T + dt_b) (reduce fused in A)
        mma_gemm<3,2><<<dim3(16, 8, 1), 256, GSMEM>>>(nullptr, 0,
            dt_w + (size_t)l * 1024 * 32, 32, dt_b + l * DINX, p_dt, 1024, 32);
        // scan (conv + B/C partial-reduce fused into staging)
        scan_kernel<<<dim3(64, 2), 256>>>(l, Dp + l * DINX,
            conv_w + (size_t)l * DINX * 4, conv_b + l * DINX);
        // hidden_partials = (y*silu(z)) @ out_proj^T (split-K 4, gate fused in A)
        mma_gemm<1,4><<<dim3(8, 8, 4), 256, GSMEM>>>(nullptr, 0,
            out_proj_w + (size_t)l * 512 * 1024, 1024, nullptr, nullptr, 512, 256);
        add_rms_kernel<4><<<TTOT, 256>>>(norm2_w + l * DMODEL);
        // g[512,2048] = xnorm @ fc1^T (K=512)
        mma_gemm<0,0><<<dim3(32, 8, 1), 256, GSMEM>>>(p_xnorm, 512,
            fc1_w + (size_t)l * 2048 * 512, 512, nullptr, p_g, 2048, 512);
        // hidden_partials = (g1*silu(g2)) @ fc2^T (split-K 4, GLU fused in A)
        mma_gemm<2,4><<<dim3(8, 8, 4), 256, GSMEM>>>(nullptr, 0,
            fc2_w + (size_t)l * 512 * 1024, 1024, nullptr, nullptr, 512, 256);
    }

    // final norm + head + loss
    add_rms_kernel<4><<<TTOT, 256>>>(norm_f_w);
    int write_preds = (out_size >= 1536) ? 1 : 0;
    int ofs = (out_size == 1536) ? 0 : 1;
    int write_loss = (out_size != 1536) ? 1 : 0;
    head_kernel<<<128, 384>>>(head_w, head_b, labels, out, ofs, write_preds);
    loss_kernel<<<1, 128>>>(seqlen, out, write_loss);
}